// round 13
// baseline (speedup 1.0000x reference)
#include <cuda_runtime.h>
#include <math.h>

#define Nn 8192
#define Cc 128
#define Ee 131072
#define ET (Ee + Nn)
#define KN 2048

#define EMAT_OFF (KN*Cc)
#define PERM_OFF (EMAT_OFF + KN*KN)
#define SVAL_OFF (PERM_OFF + KN)
#define ATT_OFF  (SVAL_OFF + ET)

// ---------------- shared CSR ------------------------------------------------
__device__ int   g_cnt[Nn], g_off[Nn+1], g_cur[Nn];
__device__ int   g_scnt[Nn], g_soff[Nn+1], g_scur[Nn];
__device__ int   g_eid[ET], g_ccol[ET], g_prow[ET];
__device__ float g_cw[ET];
__device__ int   g_inp[Nn], g_nidx[Nn];
__device__ int   g_sdp[ET];
__device__ float g_sdv[ET];

// ---------------- fp32 (emulation) buffers ----------------------------------
__device__ float g_h[Nn*Cc], g_xpool[Nn*Cc], g_xq[Nn*Cc], g_mq[Nn*Cc], g_outf[Nn*Cc];
__device__ float g_dinv[Nn], g_a1l[Nn*4];
__device__ float g_hL[Nn], g_f1b[Nn], g_f2b[Nn], g_fitf[Nn];
__device__ float g_nrm[ET], g_s[ET], g_att[ET];

// ---------------- fp64 (exact) buffers --------------------------------------
__device__ double g_hd[Nn*Cc], g_xpd[Nn*Cc], g_xqd[Nn*Cc], g_outd[Nn*Cc];
__device__ double g_dinvd[Nn], g_a1d[Nn], g_a2d[Nn], g_hLd[Nn], g_f1d[Nn], g_f2d[Nn];
__device__ double g_vd[Cc], g_b0d;
__device__ double g_sbufd[ET], g_attd[ET];
__device__ double g_fitd[Nn];

// ---------------- rankings --------------------------------------------------
__device__ int   g_ranke[Nn];
__device__ int   g_permx[KN+1];
__device__ int   g_perme[Nn];
__device__ unsigned long long g_keye[Nn];
__device__ unsigned long long g_skeye[Nn];     // chunk-sorted emulated keys
__device__ unsigned long long g_skd[Nn];       // chunk-sorted exact fitness bits
__device__ int   g_sidxd[Nn];                  // matching node indices
__device__ int   g_pa, g_pb;

// ---------------- helpers ---------------------------------------------------
__device__ __forceinline__ void edge_of(int e, const int* src, const int* dst,
                                        const float* ew, int& r, int& c, float& w) {
    if (e < Ee) { r = src[e]; c = dst[e]; w = ew[e]; }
    else        { r = e - Ee; c = r;      w = 1.0f;  }
}
__device__ __forceinline__ double wsumd(double v) {
    #pragma unroll
    for (int o = 16; o; o >>= 1) v += __shfl_xor_sync(0xffffffffu, v, o);
    return v;
}
__device__ __forceinline__ void acc2(float& s, float& c, float a, float b) {
    float p = __fmul_rn(a, b);
    float e = __fmaf_rn(a, b, -p);
    float t = s + p;
    float comp = (fabsf(s) >= fabsf(p)) ? ((s - t) + p) : ((p - t) + s);
    s = t;
    c = c + comp + e;
}
// XLA CPU VF32Exp (verbatim)
__device__ __forceinline__ float xla_expf(float x) {
    float v = fminf(fmaxf(x, -87.8f), 88.8f);
    float zm = __fmaf_rn(v, 1.44269504088896340736f, 12582912.0f);
    float k = __fadd_rn(zm, -12582912.0f);
    float r = __fmaf_rn(k, -0.693145751953125f, v);
    r = __fmaf_rn(k, -1.42860677e-6f, r);
    float p = 0.00828929059f;
    p = __fmaf_rn(p, r, 0.0418978221f);
    p = __fmaf_rn(p, r, 0.166676521f);
    p = __fmaf_rn(p, r, 0.5f);
    p = __fmaf_rn(p, r, 1.0f);
    p = __fmaf_rn(p, r, 1.0f);
    int ik = (int)k;
    return __uint_as_float(__float_as_uint(p) + ((unsigned int)ik << 23));
}
// XLA tanh rational approx (verbatim)
__device__ __forceinline__ float xla_tanh(float x) {
    const float kClamp = 7.90531110763549805f;
    float xc = fminf(fmaxf(x, -kClamp), kClamp);
    float x2 = __fmul_rn(xc, xc);
    float p = -2.76076847742355e-16f;
    p = __fmaf_rn(p, x2, 2.00018790482477e-13f);
    p = __fmaf_rn(p, x2, -8.60467152213735e-11f);
    p = __fmaf_rn(p, x2, 5.12229709037114e-08f);
    p = __fmaf_rn(p, x2, 1.48572235717979e-05f);
    p = __fmaf_rn(p, x2, 6.37261928875436e-04f);
    p = __fmaf_rn(p, x2, 4.89352455891786e-03f);
    float num = __fmul_rn(xc, p);
    float q = 1.19825839466702e-06f;
    q = __fmaf_rn(q, x2, 1.18534705686654e-04f);
    q = __fmaf_rn(q, x2, 2.26843463243900e-03f);
    q = __fmaf_rn(q, x2, 4.89352518554385e-03f);
    float r = __fdiv_rn(num, q);
    return (fabsf(x) < 0.0004f) ? x : r;
}
__device__ __forceinline__ float xla_sigmoid(float z) {
    float t = xla_tanh(__fmul_rn(0.5f, z));
    return __fadd_rn(0.5f, __fmul_rn(0.5f, t));
}

// ---------------- CSR build -------------------------------------------------
__global__ void k_init() {
    int i = blockIdx.x * blockDim.x + threadIdx.x;
    if (i < Nn) {
        g_cnt[i] = 1;
        g_scnt[i] = 0;
        g_inp[i] = 0;
        g_nidx[i] = 0;
    }
}

__global__ void k_cnt(const int* src) {
    int e = blockIdx.x * blockDim.x + threadIdx.x;
    if (e < Ee) atomicAdd(&g_cnt[src[e]], 1);
}

__global__ void k_scan(const int* cnt, int* off, int* cur) {
    __shared__ int part[1024];
    int t = threadIdx.x;
    int base = t * 8;
    int local[8];
    int s = 0;
    #pragma unroll
    for (int i = 0; i < 8; i++) { local[i] = s; s += cnt[base + i]; }
    part[t] = s;
    __syncthreads();
    for (int d = 1; d < 1024; d <<= 1) {
        int v = (t >= d) ? part[t - d] : 0;
        __syncthreads();
        part[t] += v;
        __syncthreads();
    }
    int add = (t > 0) ? part[t - 1] : 0;
    #pragma unroll
    for (int i = 0; i < 8; i++) {
        int o = add + local[i];
        off[base + i] = o;
        cur[base + i] = o;
    }
    if (t == 1023) off[Nn] = part[1023];
}

__global__ void k_scatter(const int* src, const int* dst, const float* ew) {
    int e = blockIdx.x * blockDim.x + threadIdx.x;
    if (e >= ET) return;
    int r, c; float w;
    edge_of(e, src, dst, ew, r, c, w);
    int pos = atomicAdd(&g_cur[r], 1);
    g_eid[pos] = e;
    g_ccol[pos] = c;
    g_cw[pos] = w;
    g_prow[pos] = r;
}

__global__ void k_sortrow() {
    int r = blockIdx.x * blockDim.x + threadIdx.x;
    if (r >= Nn) return;
    int beg = g_off[r], end = g_off[r + 1];
    for (int i = beg + 1; i < end; i++) {
        int ke = g_eid[i]; int kc = g_ccol[i]; float kw = g_cw[i];
        int j = i - 1;
        while (j >= beg && g_eid[j] > ke) {
            g_eid[j + 1] = g_eid[j]; g_ccol[j + 1] = g_ccol[j]; g_cw[j + 1] = g_cw[j];
            j--;
        }
        g_eid[j + 1] = ke; g_ccol[j + 1] = kc; g_cw[j + 1] = kw;
    }
}

// ================= fp32 pipeline (bit-exact emulation) ======================
__global__ void k_deg() {
    int r = blockIdx.x * blockDim.x + threadIdx.x;
    if (r >= Nn) return;
    int beg = g_off[r], end = g_off[r + 1];
    float d = 0.0f;
    for (int p = beg; p < end; p++) d = __fadd_rn(d, g_cw[p]);
    g_dinv[r] = (d > 0.0f) ? __fdiv_rn(1.0f, __fsqrt_rn(d)) : 0.0f;
}

__global__ void k_nrm() {
    int p = blockIdx.x * blockDim.x + threadIdx.x;
    if (p >= ET) return;
    g_nrm[p] = __fmul_rn(__fmul_rn(g_dinv[g_prow[p]], g_cw[p]), g_dinv[g_ccol[p]]);
}

__global__ void k_gemm_h(const float* __restrict__ X, const float* __restrict__ W) {
    __shared__ float xs[Cc];
    int i = blockIdx.x, j = threadIdx.x;
    xs[j] = X[(size_t)i * Cc + j];
    __syncthreads();
    float acc = 0.0f;
    for (int k = 0; k < Cc; k++)
        acc = __fmaf_rn(xs[k], W[k * Cc + j], acc);
    g_h[(size_t)i * Cc + j] = acc;
}

__global__ void k_gemm_mq(const float* __restrict__ W, const float* __restrict__ b) {
    __shared__ float xs[Cc];
    int i = blockIdx.x, j = threadIdx.x;
    xs[j] = g_xq[(size_t)i * Cc + j];
    __syncthreads();
    float acc = 0.0f;
    for (int k = 0; k < Cc; k++)
        acc = __fmaf_rn(xs[k], W[k * Cc + j], acc);
    g_mq[(size_t)i * Cc + j] = __fadd_rn(acc, b[j]);
}

#define CHUNK 128
__global__ void k_xpool(const float* __restrict__ bg) {
    __shared__ int sc[CHUNK];
    __shared__ float sn[CHUNK];
    int r = blockIdx.x, t = threadIdx.x;
    int beg = g_off[r], end = g_off[r + 1];
    float acc = 0.0f;
    for (int base = beg; base < end; base += CHUNK) {
        int m = min(CHUNK, end - base);
        if (t < m) { sc[t] = g_ccol[base + t]; sn[t] = g_nrm[base + t]; }
        __syncthreads();
        for (int i = 0; i < m; i++)
            acc = __fadd_rn(acc, __fmul_rn(sn[i], g_h[(size_t)sc[i] * Cc + t]));
        __syncthreads();
    }
    acc = __fadd_rn(acc, bg[t]);
    g_xpool[(size_t)r * Cc + t] = acc;
}

__global__ void k_xq() {
    __shared__ int sc[CHUNK];
    int r = blockIdx.x, t = threadIdx.x;
    int beg = g_off[r], end = g_off[r + 1];
    float acc = -INFINITY;
    for (int base = beg; base < end; base += CHUNK) {
        int m = min(CHUNK, end - base);
        if (t < m) sc[t] = g_ccol[base + t];
        __syncthreads();
        for (int i = 0; i < m; i++)
            acc = fmaxf(acc, g_xpool[(size_t)sc[i] * Cc + t]);
        __syncthreads();
    }
    g_xq[(size_t)r * Cc + t] = acc;
}

__global__ void k_a1(const float* __restrict__ Wa) {
    int n = blockIdx.x * blockDim.x + threadIdx.x;
    if (n >= Nn) return;
    const float4* mq = (const float4*)&g_mq[(size_t)n * Cc];
    const float4* wa = (const float4*)Wa;
    float l0 = 0.0f, l1 = 0.0f, l2 = 0.0f, l3 = 0.0f;
    #pragma unroll 8
    for (int i = 0; i < 32; i++) {
        float4 v = mq[i];
        float4 w = wa[i];
        l0 = __fmaf_rn(v.x, w.x, l0);
        l1 = __fmaf_rn(v.y, w.y, l1);
        l2 = __fmaf_rn(v.z, w.z, l2);
        l3 = __fmaf_rn(v.w, w.w, l3);
    }
    g_a1l[n * 4 + 0] = l0; g_a1l[n * 4 + 1] = l1;
    g_a1l[n * 4 + 2] = l2; g_a1l[n * 4 + 3] = l3;
}

__global__ void k_s(const float* __restrict__ Wa, const float* __restrict__ ba) {
    __shared__ float4 wa2[32];
    if (threadIdx.x < 32)
        wa2[threadIdx.x] = *(const float4*)(Wa + Cc + threadIdx.x * 4);
    __syncthreads();
    int p = blockIdx.x * blockDim.x + threadIdx.x;
    if (p >= ET) return;
    const float4* xp = (const float4*)&g_xpool[(size_t)g_ccol[p] * Cc];
    int r = g_prow[p];
    float l0 = g_a1l[r * 4 + 0], l1 = g_a1l[r * 4 + 1];
    float l2 = g_a1l[r * 4 + 2], l3 = g_a1l[r * 4 + 3];
    #pragma unroll 8
    for (int i = 0; i < 32; i++) {
        float4 v = xp[i];
        float4 w = wa2[i];
        l0 = __fmaf_rn(v.x, w.x, l0);
        l1 = __fmaf_rn(v.y, w.y, l1);
        l2 = __fmaf_rn(v.z, w.z, l2);
        l3 = __fmaf_rn(v.w, w.w, l3);
    }
    float acc = __fadd_rn(__fadd_rn(l0, l2), __fadd_rn(l1, l3));
    acc = __fadd_rn(acc, ba[0]);
    g_s[p] = (acc >= 0.0f) ? acc : __fmul_rn(0.2f, acc);
}

__global__ void k_soft(float* __restrict__ att_out) {
    int r = blockIdx.x * blockDim.x + threadIdx.x;
    if (r >= Nn) return;
    int beg = g_off[r], end = g_off[r + 1];
    float m = -INFINITY;
    for (int p = beg; p < end; p++) m = fmaxf(m, g_s[p]);
    float sum = 0.0f;
    for (int p = beg; p < end; p++) {
        float e = xla_expf(__fadd_rn(g_s[p], -m));
        g_att[p] = e;
        sum = __fadd_rn(sum, e);
    }
    float den = __fadd_rn(sum, 1e-16f);
    for (int p = beg; p < end; p++) {
        float a = __fdiv_rn(g_att[p], den);
        g_att[p] = a;
        att_out[g_eid[p]] = a;
    }
}

__global__ void k_out(const float* __restrict__ x) {
    __shared__ int sc[CHUNK];
    __shared__ float sa[CHUNK];
    int r = blockIdx.x, t = threadIdx.x;
    int beg = g_off[r], end = g_off[r + 1];
    float acc = 0.0f;
    for (int base = beg; base < end; base += CHUNK) {
        int m = min(CHUNK, end - base);
        if (t < m) { sc[t] = g_ccol[base + t]; sa[t] = g_att[base + t]; }
        __syncthreads();
        for (int i = 0; i < m; i++)
            acc = __fadd_rn(acc, __fmul_rn(sa[i], x[(size_t)sc[i] * Cc + t]));
        __syncthreads();
    }
    g_outf[(size_t)r * Cc + t] = acc;
}

__global__ void k_hl(const float* __restrict__ Wle, const float* __restrict__ Wle1,
                     const float* __restrict__ b1, const float* __restrict__ Wle2,
                     const float* __restrict__ b2) {
    int n = blockIdx.x * blockDim.x + threadIdx.x;
    if (n >= Nn) return;
    const float4* o  = (const float4*)&g_outf[(size_t)n * Cc];
    const float4* w0 = (const float4*)Wle;
    const float4* w1 = (const float4*)Wle1;
    const float4* w2 = (const float4*)Wle2;
    float a0 = 0, a1 = 0, a2 = 0, a3 = 0;
    float c0 = 0, c1 = 0, c2 = 0, c3 = 0;
    float d0 = 0, d1 = 0, d2 = 0, d3 = 0;
    #pragma unroll 4
    for (int i = 0; i < 32; i++) {
        float4 v = o[i];
        float4 u0 = w0[i], u1 = w1[i], u2 = w2[i];
        a0 = __fmaf_rn(v.x, u0.x, a0); a1 = __fmaf_rn(v.y, u0.y, a1);
        a2 = __fmaf_rn(v.z, u0.z, a2); a3 = __fmaf_rn(v.w, u0.w, a3);
        c0 = __fmaf_rn(v.x, u1.x, c0); c1 = __fmaf_rn(v.y, u1.y, c1);
        c2 = __fmaf_rn(v.z, u1.z, c2); c3 = __fmaf_rn(v.w, u1.w, c3);
        d0 = __fmaf_rn(v.x, u2.x, d0); d1 = __fmaf_rn(v.y, u2.y, d1);
        d2 = __fmaf_rn(v.z, u2.z, d2); d3 = __fmaf_rn(v.w, u2.w, d3);
    }
    g_hL[n]  = __fadd_rn(__fadd_rn(a0, a2), __fadd_rn(a1, a3));
    g_f1b[n] = __fadd_rn(__fadd_rn(__fadd_rn(c0, c2), __fadd_rn(c1, c3)), b1[0]);
    g_f2b[n] = __fadd_rn(__fadd_rn(__fadd_rn(d0, d2), __fadd_rn(d1, d3)), b2[0]);
}

// fitness + emulated sort key (fused)
__global__ void k_fit() {
    int r = blockIdx.x * blockDim.x + threadIdx.x;
    if (r >= Nn) return;
    int beg = g_off[r], end = g_off[r + 1];
    float deg2 = 0.0f, aggr = 0.0f;
    for (int p = beg; p < end; p++) {
        int c = g_ccol[p];
        float wle = (c == r) ? 0.0f : g_cw[p];
        deg2 = __fadd_rn(deg2, wle);
        aggr = __fadd_rn(aggr, __fmul_rn(wle, g_hL[c]));
    }
    float z = __fadd_rn(__fadd_rn(__fmul_rn(deg2, g_f1b[r]), aggr), g_f2b[r]);
    float f = xla_sigmoid(z);
    g_fitf[r] = f;
    g_keye[r] = ((unsigned long long)__float_as_uint(f) << 13)
              | (unsigned int)(Nn - 1 - r);
}

// ================= fp64 exact pipeline =======================================
__global__ void k_degs_d() {
    int r = blockIdx.x * blockDim.x + threadIdx.x;
    if (r >= Nn) return;
    int beg = g_off[r], end = g_off[r + 1];
    double s = 0.0;
    for (int p = beg; p < end; p++) s += (double)g_cw[p];
    g_dinvd[r] = (s > 0.0) ? 1.0 / sqrt(s) : 0.0;
}

__global__ void k_gemm_d(const float* __restrict__ X, const float* __restrict__ W) {
    __shared__ float xs[16][Cc];
    int col = threadIdx.x;
    int row0 = blockIdx.x * 16;
    for (int i = threadIdx.x; i < 16 * Cc; i += 128)
        xs[i >> 7][i & 127] = X[(row0 + (i >> 7)) * Cc + (i & 127)];
    __syncthreads();
    float s[16], cc[16];
    #pragma unroll
    for (int i = 0; i < 16; i++) { s[i] = 0.0f; cc[i] = 0.0f; }
    for (int k = 0; k < Cc; k++) {
        float wv = W[k * Cc + col];
        #pragma unroll
        for (int i = 0; i < 16; i++) acc2(s[i], cc[i], xs[i][k], wv);
    }
    #pragma unroll
    for (int i = 0; i < 16; i++)
        g_hd[(size_t)(row0 + i) * Cc + col] = (double)s[i] + (double)cc[i];
}

__global__ void k_xpool_d(const float* __restrict__ bg) {
    int w = (blockIdx.x * blockDim.x + threadIdx.x) >> 5;
    if (w >= Nn) return;
    int lane = threadIdx.x & 31;
    int beg = g_off[w], end = g_off[w + 1];
    double dr = g_dinvd[w];
    double a0 = (double)bg[lane * 4 + 0], a1 = (double)bg[lane * 4 + 1];
    double a2 = (double)bg[lane * 4 + 2], a3 = (double)bg[lane * 4 + 3];
    for (int p = beg; p < end; p++) {
        int c = g_ccol[p];
        double nrm = dr * (double)g_cw[p] * g_dinvd[c];
        const double* hr = &g_hd[(size_t)c * Cc + lane * 4];
        a0 += nrm * hr[0]; a1 += nrm * hr[1];
        a2 += nrm * hr[2]; a3 += nrm * hr[3];
    }
    double* xr = &g_xpd[(size_t)w * Cc + lane * 4];
    xr[0] = a0; xr[1] = a1; xr[2] = a2; xr[3] = a3;
}

__global__ void k_xq_d() {
    int w = (blockIdx.x * blockDim.x + threadIdx.x) >> 5;
    if (w >= Nn) return;
    int lane = threadIdx.x & 31;
    int beg = g_off[w], end = g_off[w + 1];
    double a0 = -INFINITY, a1 = -INFINITY, a2 = -INFINITY, a3 = -INFINITY;
    for (int p = beg; p < end; p++) {
        int c = g_ccol[p];
        const double* hr = &g_xpd[(size_t)c * Cc + lane * 4];
        a0 = fmax(a0, hr[0]); a1 = fmax(a1, hr[1]);
        a2 = fmax(a2, hr[2]); a3 = fmax(a3, hr[3]);
    }
    double* xr = &g_xqd[(size_t)w * Cc + lane * 4];
    xr[0] = a0; xr[1] = a1; xr[2] = a2; xr[3] = a3;
}

__global__ void k_vvec(const float* __restrict__ Wq, const float* __restrict__ Wa,
                       const float* __restrict__ bq) {
    int c = threadIdx.x;
    double s = 0.0;
    for (int k = 0; k < Cc; k++) s += (double)Wq[c * Cc + k] * (double)Wa[k];
    g_vd[c] = s;
    if (c == 0) {
        double b = 0.0;
        for (int k = 0; k < Cc; k++) b += (double)bq[k] * (double)Wa[k];
        g_b0d = b;
    }
}

__global__ void k_a12_d(const float* __restrict__ Wa) {
    int w = (blockIdx.x * blockDim.x + threadIdx.x) >> 5;
    if (w >= Nn) return;
    int lane = threadIdx.x & 31;
    const double* vq = &g_vd[lane * 4];
    const double* xq = &g_xqd[(size_t)w * Cc + lane * 4];
    const double* xp = &g_xpd[(size_t)w * Cc + lane * 4];
    double s1 = xq[0]*vq[0] + xq[1]*vq[1] + xq[2]*vq[2] + xq[3]*vq[3];
    double s2 = xp[0]*(double)Wa[Cc+lane*4+0] + xp[1]*(double)Wa[Cc+lane*4+1]
              + xp[2]*(double)Wa[Cc+lane*4+2] + xp[3]*(double)Wa[Cc+lane*4+3];
    s1 = wsumd(s1);
    s2 = wsumd(s2);
    if (lane == 0) { g_a1d[w] = s1 + g_b0d; g_a2d[w] = s2; }
}

__global__ void k_soft_d(const float* __restrict__ ba) {
    int w = (blockIdx.x * blockDim.x + threadIdx.x) >> 5;
    if (w >= Nn) return;
    int lane = threadIdx.x & 31;
    int beg = g_off[w], end = g_off[w + 1];
    double a1r = g_a1d[w];
    double ba0 = (double)ba[0];
    double mx = -INFINITY;
    for (int p = beg + lane; p < end; p += 32) {
        double s = a1r + g_a2d[g_ccol[p]] + ba0;
        s = (s >= 0.0) ? s : 0.2 * s;
        g_sbufd[p] = s;
        mx = fmax(mx, s);
    }
    #pragma unroll
    for (int o = 16; o; o >>= 1) mx = fmax(mx, __shfl_xor_sync(0xffffffffu, mx, o));
    double sum = 0.0;
    for (int p = beg + lane; p < end; p += 32) {
        double e = exp(g_sbufd[p] - mx);
        g_sbufd[p] = e;
        sum += e;
    }
    sum = wsumd(sum);
    double den = sum + 1e-16;
    for (int p = beg + lane; p < end; p += 32)
        g_attd[p] = g_sbufd[p] / den;
}

__global__ void k_out_d(const float* __restrict__ x) {
    int w = (blockIdx.x * blockDim.x + threadIdx.x) >> 5;
    if (w >= Nn) return;
    int lane = threadIdx.x & 31;
    int beg = g_off[w], end = g_off[w + 1];
    double a0 = 0, a1 = 0, a2 = 0, a3 = 0;
    for (int p = beg; p < end; p++) {
        int c = g_ccol[p];
        double a = g_attd[p];
        float4 xv = *(const float4*)&x[(size_t)c * Cc + lane * 4];
        a0 += a * (double)xv.x; a1 += a * (double)xv.y;
        a2 += a * (double)xv.z; a3 += a * (double)xv.w;
    }
    double* orr = &g_outd[(size_t)w * Cc + lane * 4];
    orr[0] = a0; orr[1] = a1; orr[2] = a2; orr[3] = a3;
}

__global__ void k_ledots_d(const float* __restrict__ Wle, const float* __restrict__ Wle1,
                           const float* __restrict__ Wle2) {
    int w = (blockIdx.x * blockDim.x + threadIdx.x) >> 5;
    if (w >= Nn) return;
    int lane = threadIdx.x & 31;
    const double* ov = &g_outd[(size_t)w * Cc + lane * 4];
    double s0 = 0, s1 = 0, s2 = 0;
    #pragma unroll
    for (int j = 0; j < 4; j++) {
        s0 += ov[j] * (double)Wle [lane * 4 + j];
        s1 += ov[j] * (double)Wle1[lane * 4 + j];
        s2 += ov[j] * (double)Wle2[lane * 4 + j];
    }
    s0 = wsumd(s0); s1 = wsumd(s1); s2 = wsumd(s2);
    if (lane == 0) { g_hLd[w] = s0; g_f1d[w] = s1; g_f2d[w] = s2; }
}

__global__ void k_fit_d(const float* __restrict__ b1, const float* __restrict__ b2) {
    int w = (blockIdx.x * blockDim.x + threadIdx.x) >> 5;
    if (w >= Nn) return;
    int lane = threadIdx.x & 31;
    int beg = g_off[w], end = g_off[w + 1];
    double deg2 = 0.0, aggr = 0.0;
    for (int p = beg + lane; p < end; p += 32) {
        int c = g_ccol[p];
        double wv = (c == w) ? 0.0 : (double)g_cw[p];
        deg2 += wv;
        aggr += wv * g_hLd[c];
    }
    deg2 = wsumd(deg2);
    aggr = wsumd(aggr);
    if (lane == 0) {
        double z = deg2 * (g_f1d[w] + (double)b1[0]) + aggr + g_f2d[w] + (double)b2[0];
        g_fitd[w] = 1.0 / (1.0 + exp(-z));
    }
}

// ================= O(N log N) rankings =======================================
// exact comparator: a before b  <=>  ka>kb || (ka==kb && ia<ib)
// (fitness in (0,1): positive doubles order == their u64 bit patterns)

// sort 512-key chunks of (fitd bits, idx), descending-by-comparator
__global__ void k_sortd_chunk() {
    __shared__ unsigned long long sk[512];
    __shared__ int si[512];
    int b = blockIdx.x, t = threadIdx.x;
    int base = b * 512;
    sk[t]       = (unsigned long long)__double_as_longlong(g_fitd[base + t]);
    sk[t + 256] = (unsigned long long)__double_as_longlong(g_fitd[base + t + 256]);
    si[t] = base + t;
    si[t + 256] = base + t + 256;
    __syncthreads();
    for (int k = 2; k <= 512; k <<= 1) {
        for (int j = k >> 1; j > 0; j >>= 1) {
            #pragma unroll
            for (int s = 0; s < 2; s++) {
                int i = t + s * 256;
                int ixj = i ^ j;
                if (ixj > i) {
                    unsigned long long a = sk[i], c = sk[ixj];
                    int ia = si[i], ic = si[ixj];
                    bool up = ((i & k) == 0);
                    // "c before a" = c>a || (c==a && ic<ia)
                    bool cba = (c > a) || (c == a && ic < ia);
                    bool sw = up ? cba : !cba;
                    if (sw) { sk[i] = c; sk[ixj] = a; si[i] = ic; si[ixj] = ia; }
                }
            }
            __syncthreads();
        }
    }
    g_skd[base + t] = sk[t];
    g_skd[base + t + 256] = sk[t + 256];
    g_sidxd[base + t] = si[t];
    g_sidxd[base + t + 256] = si[t + 256];
}

// exact rank via binary search over 16 sorted chunks; scatter permx
__global__ void k_rankx() {
    int i = blockIdx.x * blockDim.x + threadIdx.x;
    if (i >= Nn) return;
    unsigned long long ki = (unsigned long long)__double_as_longlong(g_fitd[i]);
    int rk = 0;
    for (int b = 0; b < 16; b++) {
        const unsigned long long* ak = g_skd + b * 512;
        const int* ai = g_sidxd + b * 512;
        int lo = 0, hi = 512;
        while (lo < hi) {
            int mid = (lo + hi) >> 1;
            unsigned long long km = ak[mid];
            bool before = (km > ki) || (km == ki && ai[mid] < i);
            if (before) lo = mid + 1; else hi = mid;
        }
        rk += lo;
    }
    if (rk <= KN) g_permx[rk] = i;
}

__global__ void k_gap() {
    __shared__ double sg[1024];
    __shared__ int si[1024];
    int t = threadIdx.x;
    double best = 1e300; int bi = 0;
    for (int i = t; i < KN; i += 1024) {
        double g = g_fitd[g_permx[i]] - g_fitd[g_permx[i + 1]];
        if (g < best || (g == best && i < bi)) { best = g; bi = i; }
    }
    sg[t] = best; si[t] = bi;
    __syncthreads();
    for (int d = 512; d; d >>= 1) {
        if (t < d) {
            if (sg[t + d] < sg[t] || (sg[t + d] == sg[t] && si[t + d] < si[t])) {
                sg[t] = sg[t + d]; si[t] = si[t + d];
            }
        }
        __syncthreads();
    }
    if (t == 0) { g_pa = g_permx[si[0]]; g_pb = g_permx[si[0] + 1]; }
}

// sort 512-key chunks of emulated u64 keys, descending (keys all distinct)
__global__ void k_sorte_chunk() {
    __shared__ unsigned long long sk[512];
    int b = blockIdx.x, t = threadIdx.x;
    int base = b * 512;
    sk[t] = g_keye[base + t];
    sk[t + 256] = g_keye[base + t + 256];
    __syncthreads();
    for (int k = 2; k <= 512; k <<= 1) {
        for (int j = k >> 1; j > 0; j >>= 1) {
            #pragma unroll
            for (int s = 0; s < 2; s++) {
                int i = t + s * 256;
                int ixj = i ^ j;
                if (ixj > i) {
                    unsigned long long a = sk[i], c = sk[ixj];
                    bool up = ((i & k) == 0);
                    bool sw = up ? (a < c) : (a > c);
                    if (sw) { sk[i] = c; sk[ixj] = a; }
                }
            }
            __syncthreads();
        }
    }
    g_skeye[base + t] = sk[t];
    g_skeye[base + t + 256] = sk[t + 256];
}

// emulated rank via binary search; writes ranke + perme
__global__ void k_ranke2() {
    int i = blockIdx.x * blockDim.x + threadIdx.x;
    if (i >= Nn) return;
    unsigned long long ki = g_keye[i];
    int rk = 0;
    for (int b = 0; b < 16; b++) {
        const unsigned long long* arr = g_skeye + b * 512;
        int lo = 0, hi = 512;
        while (lo < hi) {
            int mid = (lo + hi) >> 1;
            if (arr[mid] > ki) lo = mid + 1; else hi = mid;
        }
        rk += lo;
    }
    g_ranke[i] = rk;
    g_perme[rk] = i;
}

__global__ void k_fix() {
    int a = g_pa, b = g_pb;
    int pa = g_ranke[a], pb = g_ranke[b];
    if (pa > pb) {
        g_perme[pb] = a;
        g_perme[pa] = b;
    }
}

__global__ void k_finalize(float* __restrict__ perm_f) {
    int k = blockIdx.x * blockDim.x + threadIdx.x;
    if (k < KN) {
        int i = g_perme[k];
        g_inp[i] = 1;
        g_nidx[i] = k;
        perm_f[k] = (float)i;
    }
}

__global__ void k_xout(float* __restrict__ xo) {
    int k = blockIdx.x, t = threadIdx.x;
    int i = g_perme[k];
    xo[(size_t)k * Cc + t] = __fmul_rn(g_outf[(size_t)i * Cc + t], g_fitf[i]);
}

// ---------------- S, Emat ---------------------------------------------------
__global__ void k_sval(const int* src, const int* dst, const float* ew,
                       const float* __restrict__ att_out, float* __restrict__ sval_out) {
    int e = blockIdx.x * blockDim.x + threadIdx.x;
    if (e >= ET) return;
    int r, c; float w;
    edge_of(e, src, dst, ew, r, c, w);
    int inp = g_inp[r];
    sval_out[e] = inp ? att_out[e] : 0.0f;
    if (inp) atomicAdd(&g_scnt[c], 1);
}

__global__ void k_sdscat(const int* src, const int* dst, const float* ew,
                         const float* __restrict__ att_out) {
    int e = blockIdx.x * blockDim.x + threadIdx.x;
    if (e >= ET) return;
    int r, c; float w;
    edge_of(e, src, dst, ew, r, c, w);
    if (g_inp[r]) {
        int pos = atomicAdd(&g_scur[c], 1);
        g_sdp[pos] = g_nidx[r];
        g_sdv[pos] = att_out[e];
    }
}

__global__ void k_emat(const int* src, const int* dst, const float* ew,
                       float* __restrict__ emat) {
    int e = blockIdx.x * blockDim.x + threadIdx.x;
    if (e >= ET) return;
    int r, c; float w;
    edge_of(e, src, dst, ew, r, c, w);
    int rb = g_soff[r], re = g_soff[r + 1];
    int cb = g_soff[c], ce = g_soff[c + 1];
    for (int i = rb; i < re; i++) {
        float v1w = g_sdv[i] * w;
        float* rowp = emat + (size_t)g_sdp[i] * KN;
        for (int j = cb; j < ce; j++)
            atomicAdd(&rowp[g_sdp[j]], v1w * g_sdv[j]);
    }
}

__global__ void k_diag(float* __restrict__ emat) {
    int d = blockIdx.x * blockDim.x + threadIdx.x;
    if (d < KN) emat[(size_t)d * KN + d] = 1.0f;
}

// ---------------- launcher --------------------------------------------------
extern "C" void kernel_launch(void* const* d_in, const int* in_sizes, int n_in,
                              void* d_out, int out_size) {
    const float* x     = (const float*)d_in[0];
    const int*   src   = (const int*)d_in[1];
    const int*   dst   = (const int*)d_in[2];
    const float* ew    = (const float*)d_in[3];
    const float* W_gcn = (const float*)d_in[4];
    const float* b_gcn = (const float*)d_in[5];
    const float* Wq    = (const float*)d_in[6];
    const float* bq    = (const float*)d_in[7];
    const float* Wa    = (const float*)d_in[8];
    const float* ba    = (const float*)d_in[9];
    const float* W_le  = (const float*)d_in[10];
    const float* W_le1 = (const float*)d_in[11];
    const float* b_le1 = (const float*)d_in[12];
    const float* W_le2 = (const float*)d_in[13];
    const float* b_le2 = (const float*)d_in[14];

    float* out    = (float*)d_out;
    float* xout_o = out;
    float* emat_o = out + EMAT_OFF;
    float* perm_o = out + PERM_OFF;
    float* sval_o = out + SVAL_OFF;
    float* att_o  = out + ATT_OFF;

    cudaMemsetAsync(emat_o, 0, (size_t)KN * KN * sizeof(float));

    k_init<<<32, 256>>>();
    k_cnt<<<Ee / 256, 256>>>(src);
    {
        int* d_cnt; cudaGetSymbolAddress((void**)&d_cnt, g_cnt);
        int* d_off; cudaGetSymbolAddress((void**)&d_off, g_off);
        int* d_cur; cudaGetSymbolAddress((void**)&d_cur, g_cur);
        k_scan<<<1, 1024>>>(d_cnt, d_off, d_cur);
    }
    k_scatter<<<(ET + 255) / 256, 256>>>(src, dst, ew);
    k_sortrow<<<32, 256>>>();

    // fp32 emulation pipeline
    k_deg<<<32, 256>>>();
    k_nrm<<<(ET + 255) / 256, 256>>>();
    k_gemm_h<<<Nn, Cc>>>(x, W_gcn);
    k_xpool<<<Nn, Cc>>>(b_gcn);
    k_xq<<<Nn, Cc>>>();
    k_gemm_mq<<<Nn, Cc>>>(Wq, bq);
    k_a1<<<32, 256>>>(Wa);
    k_s<<<(ET + 255) / 256, 256>>>(Wa, ba);
    k_soft<<<32, 256>>>(att_o);
    k_out<<<Nn, Cc>>>(x);
    k_hl<<<32, 256>>>(W_le, W_le1, b_le1, W_le2, b_le2);
    k_fit<<<32, 256>>>();

    // fp64 exact pipeline
    k_degs_d<<<32, 256>>>();
    k_gemm_d<<<Nn / 16, 128>>>(x, W_gcn);
    k_xpool_d<<<Nn / 8, 256>>>(b_gcn);
    k_xq_d<<<Nn / 8, 256>>>();
    k_vvec<<<1, 128>>>(Wq, Wa, bq);
    k_a12_d<<<Nn / 8, 256>>>(Wa);
    k_soft_d<<<Nn / 8, 256>>>(ba);
    k_out_d<<<Nn / 8, 256>>>(x);
    k_ledots_d<<<Nn / 8, 256>>>(W_le, W_le1, W_le2);
    k_fit_d<<<Nn / 8, 256>>>(b_le1, b_le2);

    // O(N log N) rankings + P1 correction
    k_sortd_chunk<<<16, 256>>>();
    k_rankx<<<32, 256>>>();
    k_gap<<<1, 1024>>>();
    k_sorte_chunk<<<16, 256>>>();
    k_ranke2<<<32, 256>>>();
    k_fix<<<1, 1>>>();
    k_finalize<<<KN / 256, 256>>>(perm_o);
    k_xout<<<KN, Cc>>>(xout_o);

    // S, Emat
    k_sval<<<(ET + 255) / 256, 256>>>(src, dst, ew, att_o, sval_o);
    {
        int* d_scnt; cudaGetSymbolAddress((void**)&d_scnt, g_scnt);
        int* d_soff; cudaGetSymbolAddress((void**)&d_soff, g_soff);
        int* d_scur; cudaGetSymbolAddress((void**)&d_scur, g_scur);
        k_scan<<<1, 1024>>>(d_scnt, d_soff, d_scur);
    }
    k_sdscat<<<(ET + 255) / 256, 256>>>(src, dst, ew, att_o);
    k_emat<<<(ET + 255) / 256, 256>>>(src, dst, ew, emat_o);
    k_diag<<<KN / 256, 256>>>(emat_o);
}

// round 14
// speedup vs baseline: 1.3618x; 1.3618x over previous
#include <cuda_runtime.h>
#include <math.h>

#define Nn 8192
#define Cc 128
#define Ee 131072
#define ET (Ee + Nn)
#define KN 2048

#define EMAT_OFF (KN*Cc)
#define PERM_OFF (EMAT_OFF + KN*KN)
#define SVAL_OFF (PERM_OFF + KN)
#define ATT_OFF  (SVAL_OFF + ET)

// ---------------- shared CSR ------------------------------------------------
__device__ int   g_cnt[Nn], g_off[Nn+1], g_cur[Nn];
__device__ int   g_scnt[Nn], g_soff[Nn+1], g_scur[Nn];
__device__ int   g_eid[ET], g_ccol[ET], g_prow[ET];
__device__ float g_cw[ET];
__device__ int   g_inp[Nn], g_nidx[Nn];
__device__ int   g_sdp[ET];
__device__ float g_sdv[ET];

// ---------------- fp32 (emulation) buffers ----------------------------------
__device__ float g_h[Nn*Cc], g_xpool[Nn*Cc], g_xq[Nn*Cc], g_mq[Nn*Cc], g_outf[Nn*Cc];
__device__ float g_dinv[Nn], g_a1l[Nn*4];
__device__ float g_hL[Nn], g_f1b[Nn], g_f2b[Nn], g_fitf[Nn];
__device__ float g_nrm[ET], g_s[ET], g_att[ET];

// ---------------- fp64 (exact) buffers --------------------------------------
__device__ double g_hd[Nn*Cc], g_xpd[Nn*Cc], g_xqd[Nn*Cc], g_outd[Nn*Cc];
__device__ double g_dinvd[Nn], g_a1d[Nn], g_a2d[Nn], g_hLd[Nn], g_f1d[Nn], g_f2d[Nn];
__device__ double g_vd[Cc], g_b0d;
__device__ double g_sbufd[ET], g_attd[ET];
__device__ double g_fitd[Nn];

// ---------------- rankings --------------------------------------------------
__device__ int   g_ranke[Nn];
__device__ int   g_permx[KN+1];
__device__ int   g_perme[Nn];
__device__ unsigned long long g_keye[Nn];
__device__ unsigned long long g_skeye[Nn];
__device__ unsigned long long g_skd[Nn];
__device__ int   g_sidxd[Nn];
__device__ int   g_pa, g_pb;

// ---------------- helpers ---------------------------------------------------
__device__ __forceinline__ void edge_of(int e, const int* src, const int* dst,
                                        const float* ew, int& r, int& c, float& w) {
    if (e < Ee) { r = src[e]; c = dst[e]; w = ew[e]; }
    else        { r = e - Ee; c = r;      w = 1.0f;  }
}
__device__ __forceinline__ double wsumd(double v) {
    #pragma unroll
    for (int o = 16; o; o >>= 1) v += __shfl_xor_sync(0xffffffffu, v, o);
    return v;
}
__device__ __forceinline__ void acc2(float& s, float& c, float a, float b) {
    float p = __fmul_rn(a, b);
    float e = __fmaf_rn(a, b, -p);
    float t = s + p;
    float comp = (fabsf(s) >= fabsf(p)) ? ((s - t) + p) : ((p - t) + s);
    s = t;
    c = c + comp + e;
}
// XLA CPU VF32Exp (verbatim)
__device__ __forceinline__ float xla_expf(float x) {
    float v = fminf(fmaxf(x, -87.8f), 88.8f);
    float zm = __fmaf_rn(v, 1.44269504088896340736f, 12582912.0f);
    float k = __fadd_rn(zm, -12582912.0f);
    float r = __fmaf_rn(k, -0.693145751953125f, v);
    r = __fmaf_rn(k, -1.42860677e-6f, r);
    float p = 0.00828929059f;
    p = __fmaf_rn(p, r, 0.0418978221f);
    p = __fmaf_rn(p, r, 0.166676521f);
    p = __fmaf_rn(p, r, 0.5f);
    p = __fmaf_rn(p, r, 1.0f);
    p = __fmaf_rn(p, r, 1.0f);
    int ik = (int)k;
    return __uint_as_float(__float_as_uint(p) + ((unsigned int)ik << 23));
}
// XLA tanh rational approx (verbatim)
__device__ __forceinline__ float xla_tanh(float x) {
    const float kClamp = 7.90531110763549805f;
    float xc = fminf(fmaxf(x, -kClamp), kClamp);
    float x2 = __fmul_rn(xc, xc);
    float p = -2.76076847742355e-16f;
    p = __fmaf_rn(p, x2, 2.00018790482477e-13f);
    p = __fmaf_rn(p, x2, -8.60467152213735e-11f);
    p = __fmaf_rn(p, x2, 5.12229709037114e-08f);
    p = __fmaf_rn(p, x2, 1.48572235717979e-05f);
    p = __fmaf_rn(p, x2, 6.37261928875436e-04f);
    p = __fmaf_rn(p, x2, 4.89352455891786e-03f);
    float num = __fmul_rn(xc, p);
    float q = 1.19825839466702e-06f;
    q = __fmaf_rn(q, x2, 1.18534705686654e-04f);
    q = __fmaf_rn(q, x2, 2.26843463243900e-03f);
    q = __fmaf_rn(q, x2, 4.89352518554385e-03f);
    float r = __fdiv_rn(num, q);
    return (fabsf(x) < 0.0004f) ? x : r;
}
__device__ __forceinline__ float xla_sigmoid(float z) {
    float t = xla_tanh(__fmul_rn(0.5f, z));
    return __fadd_rn(0.5f, __fmul_rn(0.5f, t));
}

// ---------------- CSR build -------------------------------------------------
__global__ void k_init() {
    int i = blockIdx.x * blockDim.x + threadIdx.x;
    if (i < Nn) {
        g_cnt[i] = 1;
        g_scnt[i] = 0;
        g_inp[i] = 0;
        g_nidx[i] = 0;
    }
}

__global__ void k_cnt(const int* src) {
    int e = blockIdx.x * blockDim.x + threadIdx.x;
    if (e < Ee) atomicAdd(&g_cnt[src[e]], 1);
}

__global__ void k_scan(const int* cnt, int* off, int* cur) {
    __shared__ int part[1024];
    int t = threadIdx.x;
    int base = t * 8;
    int local[8];
    int s = 0;
    #pragma unroll
    for (int i = 0; i < 8; i++) { local[i] = s; s += cnt[base + i]; }
    part[t] = s;
    __syncthreads();
    for (int d = 1; d < 1024; d <<= 1) {
        int v = (t >= d) ? part[t - d] : 0;
        __syncthreads();
        part[t] += v;
        __syncthreads();
    }
    int add = (t > 0) ? part[t - 1] : 0;
    #pragma unroll
    for (int i = 0; i < 8; i++) {
        int o = add + local[i];
        off[base + i] = o;
        cur[base + i] = o;
    }
    if (t == 1023) off[Nn] = part[1023];
}

__global__ void k_scatter(const int* src, const int* dst, const float* ew) {
    int e = blockIdx.x * blockDim.x + threadIdx.x;
    if (e >= ET) return;
    int r, c; float w;
    edge_of(e, src, dst, ew, r, c, w);
    int pos = atomicAdd(&g_cur[r], 1);
    g_eid[pos] = e;
    g_ccol[pos] = c;
    g_cw[pos] = w;
    g_prow[pos] = r;
}

__global__ void k_sortrow() {
    int r = blockIdx.x * blockDim.x + threadIdx.x;
    if (r >= Nn) return;
    int beg = g_off[r], end = g_off[r + 1];
    for (int i = beg + 1; i < end; i++) {
        int ke = g_eid[i]; int kc = g_ccol[i]; float kw = g_cw[i];
        int j = i - 1;
        while (j >= beg && g_eid[j] > ke) {
            g_eid[j + 1] = g_eid[j]; g_ccol[j + 1] = g_ccol[j]; g_cw[j + 1] = g_cw[j];
            j--;
        }
        g_eid[j + 1] = ke; g_ccol[j + 1] = kc; g_cw[j + 1] = kw;
    }
}

// ================= fp32 pipeline (bit-exact emulation) ======================
__global__ void k_deg() {
    int r = blockIdx.x * blockDim.x + threadIdx.x;
    if (r >= Nn) return;
    int beg = g_off[r], end = g_off[r + 1];
    float d = 0.0f;
    for (int p = beg; p < end; p++) d = __fadd_rn(d, g_cw[p]);
    g_dinv[r] = (d > 0.0f) ? __fdiv_rn(1.0f, __fsqrt_rn(d)) : 0.0f;
}

__global__ void k_nrm() {
    int p = blockIdx.x * blockDim.x + threadIdx.x;
    if (p >= ET) return;
    g_nrm[p] = __fmul_rn(__fmul_rn(g_dinv[g_prow[p]], g_cw[p]), g_dinv[g_ccol[p]]);
}

__global__ void k_gemm_h(const float* __restrict__ X, const float* __restrict__ W) {
    __shared__ float xs[Cc];
    int i = blockIdx.x, j = threadIdx.x;
    xs[j] = X[(size_t)i * Cc + j];
    __syncthreads();
    float acc = 0.0f;
    for (int k = 0; k < Cc; k++)
        acc = __fmaf_rn(xs[k], W[k * Cc + j], acc);
    g_h[(size_t)i * Cc + j] = acc;
}

__global__ void k_gemm_mq(const float* __restrict__ W, const float* __restrict__ b) {
    __shared__ float xs[Cc];
    int i = blockIdx.x, j = threadIdx.x;
    xs[j] = g_xq[(size_t)i * Cc + j];
    __syncthreads();
    float acc = 0.0f;
    for (int k = 0; k < Cc; k++)
        acc = __fmaf_rn(xs[k], W[k * Cc + j], acc);
    g_mq[(size_t)i * Cc + j] = __fadd_rn(acc, b[j]);
}

#define CHUNK 128
__global__ void k_xpool(const float* __restrict__ bg) {
    __shared__ int sc[CHUNK];
    __shared__ float sn[CHUNK];
    int r = blockIdx.x, t = threadIdx.x;
    int beg = g_off[r], end = g_off[r + 1];
    float acc = 0.0f;
    for (int base = beg; base < end; base += CHUNK) {
        int m = min(CHUNK, end - base);
        if (t < m) { sc[t] = g_ccol[base + t]; sn[t] = g_nrm[base + t]; }
        __syncthreads();
        for (int i = 0; i < m; i++)
            acc = __fadd_rn(acc, __fmul_rn(sn[i], g_h[(size_t)sc[i] * Cc + t]));
        __syncthreads();
    }
    acc = __fadd_rn(acc, bg[t]);
    g_xpool[(size_t)r * Cc + t] = acc;
}

__global__ void k_xq() {
    __shared__ int sc[CHUNK];
    int r = blockIdx.x, t = threadIdx.x;
    int beg = g_off[r], end = g_off[r + 1];
    float acc = -INFINITY;
    for (int base = beg; base < end; base += CHUNK) {
        int m = min(CHUNK, end - base);
        if (t < m) sc[t] = g_ccol[base + t];
        __syncthreads();
        for (int i = 0; i < m; i++)
            acc = fmaxf(acc, g_xpool[(size_t)sc[i] * Cc + t]);
        __syncthreads();
    }
    g_xq[(size_t)r * Cc + t] = acc;
}

__global__ void k_a1(const float* __restrict__ Wa) {
    int n = blockIdx.x * blockDim.x + threadIdx.x;
    if (n >= Nn) return;
    const float4* mq = (const float4*)&g_mq[(size_t)n * Cc];
    const float4* wa = (const float4*)Wa;
    float l0 = 0.0f, l1 = 0.0f, l2 = 0.0f, l3 = 0.0f;
    #pragma unroll 8
    for (int i = 0; i < 32; i++) {
        float4 v = mq[i];
        float4 w = wa[i];
        l0 = __fmaf_rn(v.x, w.x, l0);
        l1 = __fmaf_rn(v.y, w.y, l1);
        l2 = __fmaf_rn(v.z, w.z, l2);
        l3 = __fmaf_rn(v.w, w.w, l3);
    }
    g_a1l[n * 4 + 0] = l0; g_a1l[n * 4 + 1] = l1;
    g_a1l[n * 4 + 2] = l2; g_a1l[n * 4 + 3] = l3;
}

__global__ void k_s(const float* __restrict__ Wa, const float* __restrict__ ba) {
    __shared__ float4 wa2[32];
    if (threadIdx.x < 32)
        wa2[threadIdx.x] = *(const float4*)(Wa + Cc + threadIdx.x * 4);
    __syncthreads();
    int p = blockIdx.x * blockDim.x + threadIdx.x;
    if (p >= ET) return;
    const float4* xp = (const float4*)&g_xpool[(size_t)g_ccol[p] * Cc];
    int r = g_prow[p];
    float l0 = g_a1l[r * 4 + 0], l1 = g_a1l[r * 4 + 1];
    float l2 = g_a1l[r * 4 + 2], l3 = g_a1l[r * 4 + 3];
    #pragma unroll 8
    for (int i = 0; i < 32; i++) {
        float4 v = xp[i];
        float4 w = wa2[i];
        l0 = __fmaf_rn(v.x, w.x, l0);
        l1 = __fmaf_rn(v.y, w.y, l1);
        l2 = __fmaf_rn(v.z, w.z, l2);
        l3 = __fmaf_rn(v.w, w.w, l3);
    }
    float acc = __fadd_rn(__fadd_rn(l0, l2), __fadd_rn(l1, l3));
    acc = __fadd_rn(acc, ba[0]);
    g_s[p] = (acc >= 0.0f) ? acc : __fmul_rn(0.2f, acc);
}

__global__ void k_soft(float* __restrict__ att_out) {
    int r = blockIdx.x * blockDim.x + threadIdx.x;
    if (r >= Nn) return;
    int beg = g_off[r], end = g_off[r + 1];
    float m = -INFINITY;
    for (int p = beg; p < end; p++) m = fmaxf(m, g_s[p]);
    float sum = 0.0f;
    for (int p = beg; p < end; p++) {
        float e = xla_expf(__fadd_rn(g_s[p], -m));
        g_att[p] = e;
        sum = __fadd_rn(sum, e);
    }
    float den = __fadd_rn(sum, 1e-16f);
    for (int p = beg; p < end; p++) {
        float a = __fdiv_rn(g_att[p], den);
        g_att[p] = a;
        att_out[g_eid[p]] = a;
    }
}

__global__ void k_out(const float* __restrict__ x) {
    __shared__ int sc[CHUNK];
    __shared__ float sa[CHUNK];
    int r = blockIdx.x, t = threadIdx.x;
    int beg = g_off[r], end = g_off[r + 1];
    float acc = 0.0f;
    for (int base = beg; base < end; base += CHUNK) {
        int m = min(CHUNK, end - base);
        if (t < m) { sc[t] = g_ccol[base + t]; sa[t] = g_att[base + t]; }
        __syncthreads();
        for (int i = 0; i < m; i++)
            acc = __fadd_rn(acc, __fmul_rn(sa[i], x[(size_t)sc[i] * Cc + t]));
        __syncthreads();
    }
    g_outf[(size_t)r * Cc + t] = acc;
}

__global__ void k_hl(const float* __restrict__ Wle, const float* __restrict__ Wle1,
                     const float* __restrict__ b1, const float* __restrict__ Wle2,
                     const float* __restrict__ b2) {
    int n = blockIdx.x * blockDim.x + threadIdx.x;
    if (n >= Nn) return;
    const float4* o  = (const float4*)&g_outf[(size_t)n * Cc];
    const float4* w0 = (const float4*)Wle;
    const float4* w1 = (const float4*)Wle1;
    const float4* w2 = (const float4*)Wle2;
    float a0 = 0, a1 = 0, a2 = 0, a3 = 0;
    float c0 = 0, c1 = 0, c2 = 0, c3 = 0;
    float d0 = 0, d1 = 0, d2 = 0, d3 = 0;
    #pragma unroll 4
    for (int i = 0; i < 32; i++) {
        float4 v = o[i];
        float4 u0 = w0[i], u1 = w1[i], u2 = w2[i];
        a0 = __fmaf_rn(v.x, u0.x, a0); a1 = __fmaf_rn(v.y, u0.y, a1);
        a2 = __fmaf_rn(v.z, u0.z, a2); a3 = __fmaf_rn(v.w, u0.w, a3);
        c0 = __fmaf_rn(v.x, u1.x, c0); c1 = __fmaf_rn(v.y, u1.y, c1);
        c2 = __fmaf_rn(v.z, u1.z, c2); c3 = __fmaf_rn(v.w, u1.w, c3);
        d0 = __fmaf_rn(v.x, u2.x, d0); d1 = __fmaf_rn(v.y, u2.y, d1);
        d2 = __fmaf_rn(v.z, u2.z, d2); d3 = __fmaf_rn(v.w, u2.w, d3);
    }
    g_hL[n]  = __fadd_rn(__fadd_rn(a0, a2), __fadd_rn(a1, a3));
    g_f1b[n] = __fadd_rn(__fadd_rn(__fadd_rn(c0, c2), __fadd_rn(c1, c3)), b1[0]);
    g_f2b[n] = __fadd_rn(__fadd_rn(__fadd_rn(d0, d2), __fadd_rn(d1, d3)), b2[0]);
}

// fitness + emulated sort key (fused)
__global__ void k_fit() {
    int r = blockIdx.x * blockDim.x + threadIdx.x;
    if (r >= Nn) return;
    int beg = g_off[r], end = g_off[r + 1];
    float deg2 = 0.0f, aggr = 0.0f;
    for (int p = beg; p < end; p++) {
        int c = g_ccol[p];
        float wle = (c == r) ? 0.0f : g_cw[p];
        deg2 = __fadd_rn(deg2, wle);
        aggr = __fadd_rn(aggr, __fmul_rn(wle, g_hL[c]));
    }
    float z = __fadd_rn(__fadd_rn(__fmul_rn(deg2, g_f1b[r]), aggr), g_f2b[r]);
    float f = xla_sigmoid(z);
    g_fitf[r] = f;
    g_keye[r] = ((unsigned long long)__float_as_uint(f) << 13)
              | (unsigned int)(Nn - 1 - r);
}

// ================= fp64 exact pipeline =======================================
__global__ void k_degs_d() {
    int r = blockIdx.x * blockDim.x + threadIdx.x;
    if (r >= Nn) return;
    int beg = g_off[r], end = g_off[r + 1];
    double s = 0.0;
    for (int p = beg; p < end; p++) s += (double)g_cw[p];
    g_dinvd[r] = (s > 0.0) ? 1.0 / sqrt(s) : 0.0;
}

__global__ void k_gemm_d(const float* __restrict__ X, const float* __restrict__ W) {
    __shared__ float xs[16][Cc];
    int col = threadIdx.x;
    int row0 = blockIdx.x * 16;
    for (int i = threadIdx.x; i < 16 * Cc; i += 128)
        xs[i >> 7][i & 127] = X[(row0 + (i >> 7)) * Cc + (i & 127)];
    __syncthreads();
    float s[16], cc[16];
    #pragma unroll
    for (int i = 0; i < 16; i++) { s[i] = 0.0f; cc[i] = 0.0f; }
    for (int k = 0; k < Cc; k++) {
        float wv = W[k * Cc + col];
        #pragma unroll
        for (int i = 0; i < 16; i++) acc2(s[i], cc[i], xs[i][k], wv);
    }
    #pragma unroll
    for (int i = 0; i < 16; i++)
        g_hd[(size_t)(row0 + i) * Cc + col] = (double)s[i] + (double)cc[i];
}

__global__ void k_xpool_d(const float* __restrict__ bg) {
    int w = (blockIdx.x * blockDim.x + threadIdx.x) >> 5;
    if (w >= Nn) return;
    int lane = threadIdx.x & 31;
    int beg = g_off[w], end = g_off[w + 1];
    double dr = g_dinvd[w];
    double a0 = (double)bg[lane * 4 + 0], a1 = (double)bg[lane * 4 + 1];
    double a2 = (double)bg[lane * 4 + 2], a3 = (double)bg[lane * 4 + 3];
    for (int p = beg; p < end; p++) {
        int c = g_ccol[p];
        double nrm = dr * (double)g_cw[p] * g_dinvd[c];
        const double* hr = &g_hd[(size_t)c * Cc + lane * 4];
        a0 += nrm * hr[0]; a1 += nrm * hr[1];
        a2 += nrm * hr[2]; a3 += nrm * hr[3];
    }
    double* xr = &g_xpd[(size_t)w * Cc + lane * 4];
    xr[0] = a0; xr[1] = a1; xr[2] = a2; xr[3] = a3;
}

__global__ void k_xq_d() {
    int w = (blockIdx.x * blockDim.x + threadIdx.x) >> 5;
    if (w >= Nn) return;
    int lane = threadIdx.x & 31;
    int beg = g_off[w], end = g_off[w + 1];
    double a0 = -INFINITY, a1 = -INFINITY, a2 = -INFINITY, a3 = -INFINITY;
    for (int p = beg; p < end; p++) {
        int c = g_ccol[p];
        const double* hr = &g_xpd[(size_t)c * Cc + lane * 4];
        a0 = fmax(a0, hr[0]); a1 = fmax(a1, hr[1]);
        a2 = fmax(a2, hr[2]); a3 = fmax(a3, hr[3]);
    }
    double* xr = &g_xqd[(size_t)w * Cc + lane * 4];
    xr[0] = a0; xr[1] = a1; xr[2] = a2; xr[3] = a3;
}

__global__ void k_vvec(const float* __restrict__ Wq, const float* __restrict__ Wa,
                       const float* __restrict__ bq) {
    int c = threadIdx.x;
    double s = 0.0;
    for (int k = 0; k < Cc; k++) s += (double)Wq[c * Cc + k] * (double)Wa[k];
    g_vd[c] = s;
    if (c == 0) {
        double b = 0.0;
        for (int k = 0; k < Cc; k++) b += (double)bq[k] * (double)Wa[k];
        g_b0d = b;
    }
}

__global__ void k_a12_d(const float* __restrict__ Wa) {
    int w = (blockIdx.x * blockDim.x + threadIdx.x) >> 5;
    if (w >= Nn) return;
    int lane = threadIdx.x & 31;
    const double* vq = &g_vd[lane * 4];
    const double* xq = &g_xqd[(size_t)w * Cc + lane * 4];
    const double* xp = &g_xpd[(size_t)w * Cc + lane * 4];
    double s1 = xq[0]*vq[0] + xq[1]*vq[1] + xq[2]*vq[2] + xq[3]*vq[3];
    double s2 = xp[0]*(double)Wa[Cc+lane*4+0] + xp[1]*(double)Wa[Cc+lane*4+1]
              + xp[2]*(double)Wa[Cc+lane*4+2] + xp[3]*(double)Wa[Cc+lane*4+3];
    s1 = wsumd(s1);
    s2 = wsumd(s2);
    if (lane == 0) { g_a1d[w] = s1 + g_b0d; g_a2d[w] = s2; }
}

__global__ void k_soft_d(const float* __restrict__ ba) {
    int w = (blockIdx.x * blockDim.x + threadIdx.x) >> 5;
    if (w >= Nn) return;
    int lane = threadIdx.x & 31;
    int beg = g_off[w], end = g_off[w + 1];
    double a1r = g_a1d[w];
    double ba0 = (double)ba[0];
    double mx = -INFINITY;
    for (int p = beg + lane; p < end; p += 32) {
        double s = a1r + g_a2d[g_ccol[p]] + ba0;
        s = (s >= 0.0) ? s : 0.2 * s;
        g_sbufd[p] = s;
        mx = fmax(mx, s);
    }
    #pragma unroll
    for (int o = 16; o; o >>= 1) mx = fmax(mx, __shfl_xor_sync(0xffffffffu, mx, o));
    double sum = 0.0;
    for (int p = beg + lane; p < end; p += 32) {
        double e = exp(g_sbufd[p] - mx);
        g_sbufd[p] = e;
        sum += e;
    }
    sum = wsumd(sum);
    double den = sum + 1e-16;
    for (int p = beg + lane; p < end; p += 32)
        g_attd[p] = g_sbufd[p] / den;
}

__global__ void k_out_d(const float* __restrict__ x) {
    int w = (blockIdx.x * blockDim.x + threadIdx.x) >> 5;
    if (w >= Nn) return;
    int lane = threadIdx.x & 31;
    int beg = g_off[w], end = g_off[w + 1];
    double a0 = 0, a1 = 0, a2 = 0, a3 = 0;
    for (int p = beg; p < end; p++) {
        int c = g_ccol[p];
        double a = g_attd[p];
        float4 xv = *(const float4*)&x[(size_t)c * Cc + lane * 4];
        a0 += a * (double)xv.x; a1 += a * (double)xv.y;
        a2 += a * (double)xv.z; a3 += a * (double)xv.w;
    }
    double* orr = &g_outd[(size_t)w * Cc + lane * 4];
    orr[0] = a0; orr[1] = a1; orr[2] = a2; orr[3] = a3;
}

__global__ void k_ledots_d(const float* __restrict__ Wle, const float* __restrict__ Wle1,
                           const float* __restrict__ Wle2) {
    int w = (blockIdx.x * blockDim.x + threadIdx.x) >> 5;
    if (w >= Nn) return;
    int lane = threadIdx.x & 31;
    const double* ov = &g_outd[(size_t)w * Cc + lane * 4];
    double s0 = 0, s1 = 0, s2 = 0;
    #pragma unroll
    for (int j = 0; j < 4; j++) {
        s0 += ov[j] * (double)Wle [lane * 4 + j];
        s1 += ov[j] * (double)Wle1[lane * 4 + j];
        s2 += ov[j] * (double)Wle2[lane * 4 + j];
    }
    s0 = wsumd(s0); s1 = wsumd(s1); s2 = wsumd(s2);
    if (lane == 0) { g_hLd[w] = s0; g_f1d[w] = s1; g_f2d[w] = s2; }
}

__global__ void k_fit_d(const float* __restrict__ b1, const float* __restrict__ b2) {
    int w = (blockIdx.x * blockDim.x + threadIdx.x) >> 5;
    if (w >= Nn) return;
    int lane = threadIdx.x & 31;
    int beg = g_off[w], end = g_off[w + 1];
    double deg2 = 0.0, aggr = 0.0;
    for (int p = beg + lane; p < end; p += 32) {
        int c = g_ccol[p];
        double wv = (c == w) ? 0.0 : (double)g_cw[p];
        deg2 += wv;
        aggr += wv * g_hLd[c];
    }
    deg2 = wsumd(deg2);
    aggr = wsumd(aggr);
    if (lane == 0) {
        double z = deg2 * (g_f1d[w] + (double)b1[0]) + aggr + g_f2d[w] + (double)b2[0];
        g_fitd[w] = 1.0 / (1.0 + exp(-z));
    }
}

// ================= O(N log N) rankings =======================================
__global__ void k_sortd_chunk() {
    __shared__ unsigned long long sk[512];
    __shared__ int si[512];
    int b = blockIdx.x, t = threadIdx.x;
    int base = b * 512;
    sk[t]       = (unsigned long long)__double_as_longlong(g_fitd[base + t]);
    sk[t + 256] = (unsigned long long)__double_as_longlong(g_fitd[base + t + 256]);
    si[t] = base + t;
    si[t + 256] = base + t + 256;
    __syncthreads();
    for (int k = 2; k <= 512; k <<= 1) {
        for (int j = k >> 1; j > 0; j >>= 1) {
            #pragma unroll
            for (int s = 0; s < 2; s++) {
                int i = t + s * 256;
                int ixj = i ^ j;
                if (ixj > i) {
                    unsigned long long a = sk[i], c = sk[ixj];
                    int ia = si[i], ic = si[ixj];
                    bool up = ((i & k) == 0);
                    bool cba = (c > a) || (c == a && ic < ia);
                    bool sw = up ? cba : !cba;
                    if (sw) { sk[i] = c; sk[ixj] = a; si[i] = ic; si[ixj] = ia; }
                }
            }
            __syncthreads();
        }
    }
    g_skd[base + t] = sk[t];
    g_skd[base + t + 256] = sk[t + 256];
    g_sidxd[base + t] = si[t];
    g_sidxd[base + t + 256] = si[t + 256];
}

__global__ void k_rankx() {
    int i = blockIdx.x * blockDim.x + threadIdx.x;
    if (i >= Nn) return;
    unsigned long long ki = (unsigned long long)__double_as_longlong(g_fitd[i]);
    int rk = 0;
    for (int b = 0; b < 16; b++) {
        const unsigned long long* ak = g_skd + b * 512;
        const int* ai = g_sidxd + b * 512;
        int lo = 0, hi = 512;
        while (lo < hi) {
            int mid = (lo + hi) >> 1;
            unsigned long long km = ak[mid];
            bool before = (km > ki) || (km == ki && ai[mid] < i);
            if (before) lo = mid + 1; else hi = mid;
        }
        rk += lo;
    }
    if (rk <= KN) g_permx[rk] = i;
}

__global__ void k_gap() {
    __shared__ double sg[1024];
    __shared__ int si[1024];
    int t = threadIdx.x;
    double best = 1e300; int bi = 0;
    for (int i = t; i < KN; i += 1024) {
        double g = g_fitd[g_permx[i]] - g_fitd[g_permx[i + 1]];
        if (g < best || (g == best && i < bi)) { best = g; bi = i; }
    }
    sg[t] = best; si[t] = bi;
    __syncthreads();
    for (int d = 512; d; d >>= 1) {
        if (t < d) {
            if (sg[t + d] < sg[t] || (sg[t + d] == sg[t] && si[t + d] < si[t])) {
                sg[t] = sg[t + d]; si[t] = si[t + d];
            }
        }
        __syncthreads();
    }
    if (t == 0) { g_pa = g_permx[si[0]]; g_pb = g_permx[si[0] + 1]; }
}

__global__ void k_sorte_chunk() {
    __shared__ unsigned long long sk[512];
    int b = blockIdx.x, t = threadIdx.x;
    int base = b * 512;
    sk[t] = g_keye[base + t];
    sk[t + 256] = g_keye[base + t + 256];
    __syncthreads();
    for (int k = 2; k <= 512; k <<= 1) {
        for (int j = k >> 1; j > 0; j >>= 1) {
            #pragma unroll
            for (int s = 0; s < 2; s++) {
                int i = t + s * 256;
                int ixj = i ^ j;
                if (ixj > i) {
                    unsigned long long a = sk[i], c = sk[ixj];
                    bool up = ((i & k) == 0);
                    bool sw = up ? (a < c) : (a > c);
                    if (sw) { sk[i] = c; sk[ixj] = a; }
                }
            }
            __syncthreads();
        }
    }
    g_skeye[base + t] = sk[t];
    g_skeye[base + t + 256] = sk[t + 256];
}

__global__ void k_ranke2() {
    int i = blockIdx.x * blockDim.x + threadIdx.x;
    if (i >= Nn) return;
    unsigned long long ki = g_keye[i];
    int rk = 0;
    for (int b = 0; b < 16; b++) {
        const unsigned long long* arr = g_skeye + b * 512;
        int lo = 0, hi = 512;
        while (lo < hi) {
            int mid = (lo + hi) >> 1;
            if (arr[mid] > ki) lo = mid + 1; else hi = mid;
        }
        rk += lo;
    }
    g_ranke[i] = rk;
    g_perme[rk] = i;
}

__global__ void k_fix() {
    int a = g_pa, b = g_pb;
    int pa = g_ranke[a], pb = g_ranke[b];
    if (pa > pb) {
        g_perme[pb] = a;
        g_perme[pa] = b;
    }
}

__global__ void k_finalize(float* __restrict__ perm_f) {
    int k = blockIdx.x * blockDim.x + threadIdx.x;
    if (k < KN) {
        int i = g_perme[k];
        g_inp[i] = 1;
        g_nidx[i] = k;
        perm_f[k] = (float)i;
    }
}

__global__ void k_xout(float* __restrict__ xo) {
    int k = blockIdx.x, t = threadIdx.x;
    int i = g_perme[k];
    xo[(size_t)k * Cc + t] = __fmul_rn(g_outf[(size_t)i * Cc + t], g_fitf[i]);
}

// ---------------- S, Emat ---------------------------------------------------
__global__ void k_sval(const int* src, const int* dst, const float* ew,
                       const float* __restrict__ att_out, float* __restrict__ sval_out) {
    int e = blockIdx.x * blockDim.x + threadIdx.x;
    if (e >= ET) return;
    int r, c; float w;
    edge_of(e, src, dst, ew, r, c, w);
    int inp = g_inp[r];
    sval_out[e] = inp ? att_out[e] : 0.0f;
    if (inp) atomicAdd(&g_scnt[c], 1);
}

__global__ void k_sdscat(const int* src, const int* dst, const float* ew,
                         const float* __restrict__ att_out) {
    int e = blockIdx.x * blockDim.x + threadIdx.x;
    if (e >= ET) return;
    int r, c; float w;
    edge_of(e, src, dst, ew, r, c, w);
    if (g_inp[r]) {
        int pos = atomicAdd(&g_scur[c], 1);
        g_sdp[pos] = g_nidx[r];
        g_sdv[pos] = att_out[e];
    }
}

__global__ void k_emat(const int* src, const int* dst, const float* ew,
                       float* __restrict__ emat) {
    int e = blockIdx.x * blockDim.x + threadIdx.x;
    if (e >= ET) return;
    int r, c; float w;
    edge_of(e, src, dst, ew, r, c, w);
    int rb = g_soff[r], re = g_soff[r + 1];
    int cb = g_soff[c], ce = g_soff[c + 1];
    for (int i = rb; i < re; i++) {
        float v1w = g_sdv[i] * w;
        float* rowp = emat + (size_t)g_sdp[i] * KN;
        for (int j = cb; j < ce; j++)
            atomicAdd(&rowp[g_sdp[j]], v1w * g_sdv[j]);
    }
}

__global__ void k_diag(float* __restrict__ emat) {
    int d = blockIdx.x * blockDim.x + threadIdx.x;
    if (d < KN) emat[(size_t)d * KN + d] = 1.0f;
}

// ---------------- launcher --------------------------------------------------
extern "C" void kernel_launch(void* const* d_in, const int* in_sizes, int n_in,
                              void* d_out, int out_size) {
    const float* x     = (const float*)d_in[0];
    const int*   src   = (const int*)d_in[1];
    const int*   dst   = (const int*)d_in[2];
    const float* ew    = (const float*)d_in[3];
    const float* W_gcn = (const float*)d_in[4];
    const float* b_gcn = (const float*)d_in[5];
    const float* Wq    = (const float*)d_in[6];
    const float* bq    = (const float*)d_in[7];
    const float* Wa    = (const float*)d_in[8];
    const float* ba    = (const float*)d_in[9];
    const float* W_le  = (const float*)d_in[10];
    const float* W_le1 = (const float*)d_in[11];
    const float* b_le1 = (const float*)d_in[12];
    const float* W_le2 = (const float*)d_in[13];
    const float* b_le2 = (const float*)d_in[14];

    float* out    = (float*)d_out;
    float* xout_o = out;
    float* emat_o = out + EMAT_OFF;
    float* perm_o = out + PERM_OFF;
    float* sval_o = out + SVAL_OFF;
    float* att_o  = out + ATT_OFF;

    // fork-join stream for the fp64 branch (created per call; leaked — streams
    // captured into a graph must not be destroyed during capture)
    cudaStream_t s2;
    cudaStreamCreate(&s2);
    cudaEvent_t evRoot, evCSR, evJoin;
    cudaEventCreateWithFlags(&evRoot, cudaEventDisableTiming);
    cudaEventCreateWithFlags(&evCSR, cudaEventDisableTiming);
    cudaEventCreateWithFlags(&evJoin, cudaEventDisableTiming);

    cudaMemsetAsync(emat_o, 0, (size_t)KN * KN * sizeof(float));
    cudaEventRecord(evRoot, 0);
    cudaStreamWaitEvent(s2, evRoot, 0);

    // s2: CSR-independent fp64 prep overlaps CSR build
    k_gemm_d<<<Nn / 16, 128, 0, s2>>>(x, W_gcn);
    k_vvec<<<1, 128, 0, s2>>>(Wq, Wa, bq);

    // stream0: CSR build
    k_init<<<32, 256>>>();
    k_cnt<<<Ee / 256, 256>>>(src);
    {
        int* d_cnt; cudaGetSymbolAddress((void**)&d_cnt, g_cnt);
        int* d_off; cudaGetSymbolAddress((void**)&d_off, g_off);
        int* d_cur; cudaGetSymbolAddress((void**)&d_cur, g_cur);
        k_scan<<<1, 1024>>>(d_cnt, d_off, d_cur);
    }
    k_scatter<<<(ET + 255) / 256, 256>>>(src, dst, ew);
    k_sortrow<<<32, 256>>>();
    cudaEventRecord(evCSR, 0);

    // s2: fp64 exact pipeline (after CSR)
    cudaStreamWaitEvent(s2, evCSR, 0);
    k_degs_d<<<32, 256, 0, s2>>>();
    k_xpool_d<<<Nn / 8, 256, 0, s2>>>(b_gcn);
    k_xq_d<<<Nn / 8, 256, 0, s2>>>();
    k_a12_d<<<Nn / 8, 256, 0, s2>>>(Wa);
    k_soft_d<<<Nn / 8, 256, 0, s2>>>(ba);
    k_out_d<<<Nn / 8, 256, 0, s2>>>(x);
    k_ledots_d<<<Nn / 8, 256, 0, s2>>>(W_le, W_le1, W_le2);
    k_fit_d<<<Nn / 8, 256, 0, s2>>>(b_le1, b_le2);
    k_sortd_chunk<<<16, 256, 0, s2>>>();
    k_rankx<<<32, 256, 0, s2>>>();
    k_gap<<<1, 1024, 0, s2>>>();
    cudaEventRecord(evJoin, s2);

    // stream0: fp32 emulation pipeline (concurrent with s2)
    k_deg<<<32, 256>>>();
    k_nrm<<<(ET + 255) / 256, 256>>>();
    k_gemm_h<<<Nn, Cc>>>(x, W_gcn);
    k_xpool<<<Nn, Cc>>>(b_gcn);
    k_xq<<<Nn, Cc>>>();
    k_gemm_mq<<<Nn, Cc>>>(Wq, bq);
    k_a1<<<32, 256>>>(Wa);
    k_s<<<(ET + 255) / 256, 256>>>(Wa, ba);
    k_soft<<<32, 256>>>(att_o);
    k_out<<<Nn, Cc>>>(x);
    k_hl<<<32, 256>>>(W_le, W_le1, b_le1, W_le2, b_le2);
    k_fit<<<32, 256>>>();
    k_sorte_chunk<<<16, 256>>>();
    k_ranke2<<<32, 256>>>();

    // join + finalize
    cudaStreamWaitEvent(0, evJoin, 0);
    k_fix<<<1, 1>>>();
    k_finalize<<<KN / 256, 256>>>(perm_o);
    k_xout<<<KN, Cc>>>(xout_o);

    // S, Emat
    k_sval<<<(ET + 255) / 256, 256>>>(src, dst, ew, att_o, sval_o);
    {
        int* d_scnt; cudaGetSymbolAddress((void**)&d_scnt, g_scnt);
        int* d_soff; cudaGetSymbolAddress((void**)&d_soff, g_soff);
        int* d_scur; cudaGetSymbolAddress((void**)&d_scur, g_scur);
        k_scan<<<1, 1024>>>(d_scnt, d_soff, d_scur);
    }
    k_sdscat<<<(ET + 255) / 256, 256>>>(src, dst, ew, att_o);
    k_emat<<<(ET + 255) / 256, 256>>>(src, dst, ew, emat_o);
    k_diag<<<KN / 256, 256>>>(emat_o);
}

// round 16
// speedup vs baseline: 1.3962x; 1.0253x over previous
#include <cuda_runtime.h>
#include <math.h>

#define Nn 8192
#define Cc 128
#define Ee 131072
#define ET (Ee + Nn)
#define KN 2048

#define EMAT_OFF (KN*Cc)
#define PERM_OFF (EMAT_OFF + KN*KN)
#define SVAL_OFF (PERM_OFF + KN)
#define ATT_OFF  (SVAL_OFF + ET)

// ---------------- shared CSR ------------------------------------------------
__device__ int   g_cnt[Nn], g_off[Nn+1], g_cur[Nn];
__device__ int   g_scnt[Nn], g_soff[Nn+1], g_scur[Nn];
__device__ int   g_eid[ET], g_ccol[ET], g_prow[ET];
__device__ float g_cw[ET];
__device__ int   g_inp[Nn], g_nidx[Nn];
__device__ int   g_sdp[ET];
__device__ float g_sdv[ET];

// ---------------- fp32 (emulation) buffers ----------------------------------
__device__ float g_h[Nn*Cc], g_xpool[Nn*Cc], g_outf[Nn*Cc];
__device__ float g_dinv[Nn], g_a1l[Nn*4];
__device__ float g_hL[Nn], g_f1b[Nn], g_f2b[Nn], g_fitf[Nn];
__device__ float g_nrm[ET], g_s[ET], g_att[ET];

// ---------------- fp64 (exact) buffers --------------------------------------
__device__ double g_hd[Nn*Cc], g_xpd[Nn*Cc], g_outd[Nn*Cc];
__device__ double g_dinvd[Nn], g_a1d[Nn], g_a2d[Nn], g_hLd[Nn], g_f1d[Nn], g_f2d[Nn];
__device__ double g_vd[Cc], g_b0d;
__device__ double g_sbufd[ET], g_attd[ET];
__device__ double g_fitd[Nn];

// ---------------- rankings --------------------------------------------------
__device__ int   g_ranke[Nn];
__device__ int   g_permx[KN+1];
__device__ int   g_perme[Nn];
__device__ unsigned long long g_keye[Nn];
__device__ unsigned long long g_skeye[Nn];
__device__ unsigned long long g_skd[Nn];
__device__ int   g_sidxd[Nn];
__device__ int   g_pa, g_pb;

// ---------------- helpers ---------------------------------------------------
__device__ __forceinline__ void edge_of(int e, const int* src, const int* dst,
                                        const float* ew, int& r, int& c, float& w) {
    if (e < Ee) { r = src[e]; c = dst[e]; w = ew[e]; }
    else        { r = e - Ee; c = r;      w = 1.0f;  }
}
__device__ __forceinline__ double wsumd(double v) {
    #pragma unroll
    for (int o = 16; o; o >>= 1) v += __shfl_xor_sync(0xffffffffu, v, o);
    return v;
}
__device__ __forceinline__ void acc2(float& s, float& c, float a, float b) {
    float p = __fmul_rn(a, b);
    float e = __fmaf_rn(a, b, -p);
    float t = s + p;
    float comp = (fabsf(s) >= fabsf(p)) ? ((s - t) + p) : ((p - t) + s);
    s = t;
    c = c + comp + e;
}
// XLA CPU VF32Exp (verbatim)
__device__ __forceinline__ float xla_expf(float x) {
    float v = fminf(fmaxf(x, -87.8f), 88.8f);
    float zm = __fmaf_rn(v, 1.44269504088896340736f, 12582912.0f);
    float k = __fadd_rn(zm, -12582912.0f);
    float r = __fmaf_rn(k, -0.693145751953125f, v);
    r = __fmaf_rn(k, -1.42860677e-6f, r);
    float p = 0.00828929059f;
    p = __fmaf_rn(p, r, 0.0418978221f);
    p = __fmaf_rn(p, r, 0.166676521f);
    p = __fmaf_rn(p, r, 0.5f);
    p = __fmaf_rn(p, r, 1.0f);
    p = __fmaf_rn(p, r, 1.0f);
    int ik = (int)k;
    return __uint_as_float(__float_as_uint(p) + ((unsigned int)ik << 23));
}
// XLA tanh rational approx (verbatim)
__device__ __forceinline__ float xla_tanh(float x) {
    const float kClamp = 7.90531110763549805f;
    float xc = fminf(fmaxf(x, -kClamp), kClamp);
    float x2 = __fmul_rn(xc, xc);
    float p = -2.76076847742355e-16f;
    p = __fmaf_rn(p, x2, 2.00018790482477e-13f);
    p = __fmaf_rn(p, x2, -8.60467152213735e-11f);
    p = __fmaf_rn(p, x2, 5.12229709037114e-08f);
    p = __fmaf_rn(p, x2, 1.48572235717979e-05f);
    p = __fmaf_rn(p, x2, 6.37261928875436e-04f);
    p = __fmaf_rn(p, x2, 4.89352455891786e-03f);
    float num = __fmul_rn(xc, p);
    float q = 1.19825839466702e-06f;
    q = __fmaf_rn(q, x2, 1.18534705686654e-04f);
    q = __fmaf_rn(q, x2, 2.26843463243900e-03f);
    q = __fmaf_rn(q, x2, 4.89352518554385e-03f);
    float r = __fdiv_rn(num, q);
    return (fabsf(x) < 0.0004f) ? x : r;
}
__device__ __forceinline__ float xla_sigmoid(float z) {
    float t = xla_tanh(__fmul_rn(0.5f, z));
    return __fadd_rn(0.5f, __fmul_rn(0.5f, t));
}

// ---------------- CSR build -------------------------------------------------
__global__ void k_init() {
    int i = blockIdx.x * blockDim.x + threadIdx.x;
    if (i < Nn) {
        g_cnt[i] = 1;
        g_scnt[i] = 0;
        g_inp[i] = 0;
        g_nidx[i] = 0;
    }
}

__global__ void k_cnt(const int* src) {
    int e = blockIdx.x * blockDim.x + threadIdx.x;
    if (e < Ee) atomicAdd(&g_cnt[src[e]], 1);
}

__global__ void k_scan(const int* cnt, int* off, int* cur) {
    __shared__ int part[1024];
    int t = threadIdx.x;
    int base = t * 8;
    int local[8];
    int s = 0;
    #pragma unroll
    for (int i = 0; i < 8; i++) { local[i] = s; s += cnt[base + i]; }
    part[t] = s;
    __syncthreads();
    for (int d = 1; d < 1024; d <<= 1) {
        int v = (t >= d) ? part[t - d] : 0;
        __syncthreads();
        part[t] += v;
        __syncthreads();
    }
    int add = (t > 0) ? part[t - 1] : 0;
    #pragma unroll
    for (int i = 0; i < 8; i++) {
        int o = add + local[i];
        off[base + i] = o;
        cur[base + i] = o;
    }
    if (t == 1023) off[Nn] = part[1023];
}

__global__ void k_scatter(const int* src, const int* dst, const float* ew) {
    int e = blockIdx.x * blockDim.x + threadIdx.x;
    if (e >= ET) return;
    int r, c; float w;
    edge_of(e, src, dst, ew, r, c, w);
    int pos = atomicAdd(&g_cur[r], 1);
    g_eid[pos] = e;
    g_ccol[pos] = c;
    g_cw[pos] = w;
    g_prow[pos] = r;
}

__global__ void k_sortrow() {
    int r = blockIdx.x * blockDim.x + threadIdx.x;
    if (r >= Nn) return;
    int beg = g_off[r], end = g_off[r + 1];
    for (int i = beg + 1; i < end; i++) {
        int ke = g_eid[i]; int kc = g_ccol[i]; float kw = g_cw[i];
        int j = i - 1;
        while (j >= beg && g_eid[j] > ke) {
            g_eid[j + 1] = g_eid[j]; g_ccol[j + 1] = g_ccol[j]; g_cw[j + 1] = g_cw[j];
            j--;
        }
        g_eid[j + 1] = ke; g_ccol[j + 1] = kc; g_cw[j + 1] = kw;
    }
}

// ================= fp32 pipeline (bit-exact emulation) ======================
__global__ void k_deg() {
    int r = blockIdx.x * blockDim.x + threadIdx.x;
    if (r >= Nn) return;
    int beg = g_off[r], end = g_off[r + 1];
    float d = 0.0f;
    for (int p = beg; p < end; p++) d = __fadd_rn(d, g_cw[p]);
    g_dinv[r] = (d > 0.0f) ? __fdiv_rn(1.0f, __fsqrt_rn(d)) : 0.0f;
}

__global__ void k_nrm() {
    int p = blockIdx.x * blockDim.x + threadIdx.x;
    if (p >= ET) return;
    g_nrm[p] = __fmul_rn(__fmul_rn(g_dinv[g_prow[p]], g_cw[p]), g_dinv[g_ccol[p]]);
}

__global__ void k_gemm_h(const float* __restrict__ X, const float* __restrict__ W) {
    __shared__ float xs[Cc];
    int i = blockIdx.x, j = threadIdx.x;
    xs[j] = X[(size_t)i * Cc + j];
    __syncthreads();
    float acc = 0.0f;
    for (int k = 0; k < Cc; k++)
        acc = __fmaf_rn(xs[k], W[k * Cc + j], acc);
    g_h[(size_t)i * Cc + j] = acc;
}

#define CHUNK 128
__global__ void k_xpool(const float* __restrict__ bg) {
    __shared__ int sc[CHUNK];
    __shared__ float sn[CHUNK];
    int r = blockIdx.x, t = threadIdx.x;
    int beg = g_off[r], end = g_off[r + 1];
    float acc = 0.0f;
    for (int base = beg; base < end; base += CHUNK) {
        int m = min(CHUNK, end - base);
        if (t < m) { sc[t] = g_ccol[base + t]; sn[t] = g_nrm[base + t]; }
        __syncthreads();
        for (int i = 0; i < m; i++)
            acc = __fadd_rn(acc, __fmul_rn(sn[i], g_h[(size_t)sc[i] * Cc + t]));
        __syncthreads();
    }
    acc = __fadd_rn(acc, bg[t]);
    g_xpool[(size_t)r * Cc + t] = acc;
}

// fused: xq row -> mq row -> a1 lane partials (bit-exact chains)
__global__ void k_xqmq(const float* __restrict__ Wq, const float* __restrict__ bq,
                       const float* __restrict__ Wa) {
    __shared__ int sc[CHUNK];
    __shared__ float xqs[Cc];
    __shared__ float mqs[Cc];
    int r = blockIdx.x, t = threadIdx.x;
    int beg = g_off[r], end = g_off[r + 1];
    float acc = -INFINITY;
    for (int base = beg; base < end; base += CHUNK) {
        int m = min(CHUNK, end - base);
        if (t < m) sc[t] = g_ccol[base + t];
        __syncthreads();
        for (int i = 0; i < m; i++)
            acc = fmaxf(acc, g_xpool[(size_t)sc[i] * Cc + t]);
        __syncthreads();
    }
    xqs[t] = acc;
    __syncthreads();
    float mv = 0.0f;
    for (int k = 0; k < Cc; k++)
        mv = __fmaf_rn(xqs[k], Wq[k * Cc + t], mv);
    mqs[t] = __fadd_rn(mv, bq[t]);
    __syncthreads();
    if (t < 4) {
        float l = 0.0f;
        for (int i = 0; i < 32; i++)
            l = __fmaf_rn(mqs[i * 4 + t], Wa[i * 4 + t], l);
        g_a1l[r * 4 + t] = l;
    }
}

__global__ void k_s(const float* __restrict__ Wa, const float* __restrict__ ba) {
    __shared__ float4 wa2[32];
    if (threadIdx.x < 32)
        wa2[threadIdx.x] = *(const float4*)(Wa + Cc + threadIdx.x * 4);
    __syncthreads();
    int p = blockIdx.x * blockDim.x + threadIdx.x;
    if (p >= ET) return;
    const float4* xp = (const float4*)&g_xpool[(size_t)g_ccol[p] * Cc];
    int r = g_prow[p];
    float l0 = g_a1l[r * 4 + 0], l1 = g_a1l[r * 4 + 1];
    float l2 = g_a1l[r * 4 + 2], l3 = g_a1l[r * 4 + 3];
    #pragma unroll 8
    for (int i = 0; i < 32; i++) {
        float4 v = xp[i];
        float4 w = wa2[i];
        l0 = __fmaf_rn(v.x, w.x, l0);
        l1 = __fmaf_rn(v.y, w.y, l1);
        l2 = __fmaf_rn(v.z, w.z, l2);
        l3 = __fmaf_rn(v.w, w.w, l3);
    }
    float acc = __fadd_rn(__fadd_rn(l0, l2), __fadd_rn(l1, l3));
    acc = __fadd_rn(acc, ba[0]);
    g_s[p] = (acc >= 0.0f) ? acc : __fmul_rn(0.2f, acc);
}

__global__ void k_soft(float* __restrict__ att_out) {
    int r = blockIdx.x * blockDim.x + threadIdx.x;
    if (r >= Nn) return;
    int beg = g_off[r], end = g_off[r + 1];
    float m = -INFINITY;
    for (int p = beg; p < end; p++) m = fmaxf(m, g_s[p]);
    float sum = 0.0f;
    for (int p = beg; p < end; p++) {
        float e = xla_expf(__fadd_rn(g_s[p], -m));
        g_att[p] = e;
        sum = __fadd_rn(sum, e);
    }
    float den = __fadd_rn(sum, 1e-16f);
    for (int p = beg; p < end; p++) {
        float a = __fdiv_rn(g_att[p], den);
        g_att[p] = a;
        att_out[g_eid[p]] = a;
    }
}

__global__ void k_out(const float* __restrict__ x) {
    __shared__ int sc[CHUNK];
    __shared__ float sa[CHUNK];
    int r = blockIdx.x, t = threadIdx.x;
    int beg = g_off[r], end = g_off[r + 1];
    float acc = 0.0f;
    for (int base = beg; base < end; base += CHUNK) {
        int m = min(CHUNK, end - base);
        if (t < m) { sc[t] = g_ccol[base + t]; sa[t] = g_att[base + t]; }
        __syncthreads();
        for (int i = 0; i < m; i++)
            acc = __fadd_rn(acc, __fmul_rn(sa[i], x[(size_t)sc[i] * Cc + t]));
        __syncthreads();
    }
    g_outf[(size_t)r * Cc + t] = acc;
}

__global__ void k_hl(const float* __restrict__ Wle, const float* __restrict__ Wle1,
                     const float* __restrict__ b1, const float* __restrict__ Wle2,
                     const float* __restrict__ b2) {
    int n = blockIdx.x * blockDim.x + threadIdx.x;
    if (n >= Nn) return;
    const float4* o  = (const float4*)&g_outf[(size_t)n * Cc];
    const float4* w0 = (const float4*)Wle;
    const float4* w1 = (const float4*)Wle1;
    const float4* w2 = (const float4*)Wle2;
    float a0 = 0, a1 = 0, a2 = 0, a3 = 0;
    float c0 = 0, c1 = 0, c2 = 0, c3 = 0;
    float d0 = 0, d1 = 0, d2 = 0, d3 = 0;
    #pragma unroll 4
    for (int i = 0; i < 32; i++) {
        float4 v = o[i];
        float4 u0 = w0[i], u1 = w1[i], u2 = w2[i];
        a0 = __fmaf_rn(v.x, u0.x, a0); a1 = __fmaf_rn(v.y, u0.y, a1);
        a2 = __fmaf_rn(v.z, u0.z, a2); a3 = __fmaf_rn(v.w, u0.w, a3);
        c0 = __fmaf_rn(v.x, u1.x, c0); c1 = __fmaf_rn(v.y, u1.y, c1);
        c2 = __fmaf_rn(v.z, u1.z, c2); c3 = __fmaf_rn(v.w, u1.w, c3);
        d0 = __fmaf_rn(v.x, u2.x, d0); d1 = __fmaf_rn(v.y, u2.y, d1);
        d2 = __fmaf_rn(v.z, u2.z, d2); d3 = __fmaf_rn(v.w, u2.w, d3);
    }
    g_hL[n]  = __fadd_rn(__fadd_rn(a0, a2), __fadd_rn(a1, a3));
    g_f1b[n] = __fadd_rn(__fadd_rn(__fadd_rn(c0, c2), __fadd_rn(c1, c3)), b1[0]);
    g_f2b[n] = __fadd_rn(__fadd_rn(__fadd_rn(d0, d2), __fadd_rn(d1, d3)), b2[0]);
}

__global__ void k_fit() {
    int r = blockIdx.x * blockDim.x + threadIdx.x;
    if (r >= Nn) return;
    int beg = g_off[r], end = g_off[r + 1];
    float deg2 = 0.0f, aggr = 0.0f;
    for (int p = beg; p < end; p++) {
        int c = g_ccol[p];
        float wle = (c == r) ? 0.0f : g_cw[p];
        deg2 = __fadd_rn(deg2, wle);
        aggr = __fadd_rn(aggr, __fmul_rn(wle, g_hL[c]));
    }
    float z = __fadd_rn(__fadd_rn(__fmul_rn(deg2, g_f1b[r]), aggr), g_f2b[r]);
    float f = xla_sigmoid(z);
    g_fitf[r] = f;
    g_keye[r] = ((unsigned long long)__float_as_uint(f) << 13)
              | (unsigned int)(Nn - 1 - r);
}

// ================= fp64 exact pipeline =======================================
__global__ void k_degs_d() {
    int r = blockIdx.x * blockDim.x + threadIdx.x;
    if (r >= Nn) return;
    int beg = g_off[r], end = g_off[r + 1];
    double s = 0.0;
    for (int p = beg; p < end; p++) s += (double)g_cw[p];
    g_dinvd[r] = (s > 0.0) ? 1.0 / sqrt(s) : 0.0;
}

__global__ void k_gemm_d(const float* __restrict__ X, const float* __restrict__ W) {
    __shared__ float xs[16][Cc];
    int col = threadIdx.x;
    int row0 = blockIdx.x * 16;
    for (int i = threadIdx.x; i < 16 * Cc; i += 128)
        xs[i >> 7][i & 127] = X[(row0 + (i >> 7)) * Cc + (i & 127)];
    __syncthreads();
    float s[16], cc[16];
    #pragma unroll
    for (int i = 0; i < 16; i++) { s[i] = 0.0f; cc[i] = 0.0f; }
    for (int k = 0; k < Cc; k++) {
        float wv = W[k * Cc + col];
        #pragma unroll
        for (int i = 0; i < 16; i++) acc2(s[i], cc[i], xs[i][k], wv);
    }
    #pragma unroll
    for (int i = 0; i < 16; i++)
        g_hd[(size_t)(row0 + i) * Cc + col] = (double)s[i] + (double)cc[i];
}

__global__ void k_xpool_d(const float* __restrict__ bg) {
    int w = (blockIdx.x * blockDim.x + threadIdx.x) >> 5;
    if (w >= Nn) return;
    int lane = threadIdx.x & 31;
    int beg = g_off[w], end = g_off[w + 1];
    double dr = g_dinvd[w];
    double a0 = (double)bg[lane * 4 + 0], a1 = (double)bg[lane * 4 + 1];
    double a2 = (double)bg[lane * 4 + 2], a3 = (double)bg[lane * 4 + 3];
    for (int p = beg; p < end; p++) {
        int c = g_ccol[p];
        double nrm = dr * (double)g_cw[p] * g_dinvd[c];
        const double* hr = &g_hd[(size_t)c * Cc + lane * 4];
        a0 += nrm * hr[0]; a1 += nrm * hr[1];
        a2 += nrm * hr[2]; a3 += nrm * hr[3];
    }
    double* xr = &g_xpd[(size_t)w * Cc + lane * 4];
    xr[0] = a0; xr[1] = a1; xr[2] = a2; xr[3] = a3;
}

__global__ void k_vvec(const float* __restrict__ Wq, const float* __restrict__ Wa,
                       const float* __restrict__ bq) {
    int c = threadIdx.x;
    double s = 0.0;
    for (int k = 0; k < Cc; k++) s += (double)Wq[c * Cc + k] * (double)Wa[k];
    g_vd[c] = s;
    if (c == 0) {
        double b = 0.0;
        for (int k = 0; k < Cc; k++) b += (double)bq[k] * (double)Wa[k];
        g_b0d = b;
    }
}

// fused: xq_d gather + a12_d (identical arithmetic)
__global__ void k_xqa12_d(const float* __restrict__ Wa) {
    int w = (blockIdx.x * blockDim.x + threadIdx.x) >> 5;
    if (w >= Nn) return;
    int lane = threadIdx.x & 31;
    int beg = g_off[w], end = g_off[w + 1];
    double a0 = -INFINITY, a1 = -INFINITY, a2 = -INFINITY, a3 = -INFINITY;
    for (int p = beg; p < end; p++) {
        int c = g_ccol[p];
        const double* hr = &g_xpd[(size_t)c * Cc + lane * 4];
        a0 = fmax(a0, hr[0]); a1 = fmax(a1, hr[1]);
        a2 = fmax(a2, hr[2]); a3 = fmax(a3, hr[3]);
    }
    const double* vq = &g_vd[lane * 4];
    const double* xp = &g_xpd[(size_t)w * Cc + lane * 4];
    double s1 = a0*vq[0] + a1*vq[1] + a2*vq[2] + a3*vq[3];
    double s2 = xp[0]*(double)Wa[Cc+lane*4+0] + xp[1]*(double)Wa[Cc+lane*4+1]
              + xp[2]*(double)Wa[Cc+lane*4+2] + xp[3]*(double)Wa[Cc+lane*4+3];
    s1 = wsumd(s1);
    s2 = wsumd(s2);
    if (lane == 0) { g_a1d[w] = s1 + g_b0d; g_a2d[w] = s2; }
}

__global__ void k_soft_d(const float* __restrict__ ba) {
    int w = (blockIdx.x * blockDim.x + threadIdx.x) >> 5;
    if (w >= Nn) return;
    int lane = threadIdx.x & 31;
    int beg = g_off[w], end = g_off[w + 1];
    double a1r = g_a1d[w];
    double ba0 = (double)ba[0];
    double mx = -INFINITY;
    for (int p = beg + lane; p < end; p += 32) {
        double s = a1r + g_a2d[g_ccol[p]] + ba0;
        s = (s >= 0.0) ? s : 0.2 * s;
        g_sbufd[p] = s;
        mx = fmax(mx, s);
    }
    #pragma unroll
    for (int o = 16; o; o >>= 1) mx = fmax(mx, __shfl_xor_sync(0xffffffffu, mx, o));
    double sum = 0.0;
    for (int p = beg + lane; p < end; p += 32) {
        double e = exp(g_sbufd[p] - mx);
        g_sbufd[p] = e;
        sum += e;
    }
    sum = wsumd(sum);
    double den = sum + 1e-16;
    for (int p = beg + lane; p < end; p += 32)
        g_attd[p] = g_sbufd[p] / den;
}

__global__ void k_out_d(const float* __restrict__ x) {
    int w = (blockIdx.x * blockDim.x + threadIdx.x) >> 5;
    if (w >= Nn) return;
    int lane = threadIdx.x & 31;
    int beg = g_off[w], end = g_off[w + 1];
    double a0 = 0, a1 = 0, a2 = 0, a3 = 0;
    for (int p = beg; p < end; p++) {
        int c = g_ccol[p];
        double a = g_attd[p];
        float4 xv = *(const float4*)&x[(size_t)c * Cc + lane * 4];
        a0 += a * (double)xv.x; a1 += a * (double)xv.y;
        a2 += a * (double)xv.z; a3 += a * (double)xv.w;
    }
    double* orr = &g_outd[(size_t)w * Cc + lane * 4];
    orr[0] = a0; orr[1] = a1; orr[2] = a2; orr[3] = a3;
}

__global__ void k_ledots_d(const float* __restrict__ Wle, const float* __restrict__ Wle1,
                           const float* __restrict__ Wle2) {
    int w = (blockIdx.x * blockDim.x + threadIdx.x) >> 5;
    if (w >= Nn) return;
    int lane = threadIdx.x & 31;
    const double* ov = &g_outd[(size_t)w * Cc + lane * 4];
    double s0 = 0, s1 = 0, s2 = 0;
    #pragma unroll
    for (int j = 0; j < 4; j++) {
        s0 += ov[j] * (double)Wle [lane * 4 + j];
        s1 += ov[j] * (double)Wle1[lane * 4 + j];
        s2 += ov[j] * (double)Wle2[lane * 4 + j];
    }
    s0 = wsumd(s0); s1 = wsumd(s1); s2 = wsumd(s2);
    if (lane == 0) { g_hLd[w] = s0; g_f1d[w] = s1; g_f2d[w] = s2; }
}

__global__ void k_fit_d(const float* __restrict__ b1, const float* __restrict__ b2) {
    int w = (blockIdx.x * blockDim.x + threadIdx.x) >> 5;
    if (w >= Nn) return;
    int lane = threadIdx.x & 31;
    int beg = g_off[w], end = g_off[w + 1];
    double deg2 = 0.0, aggr = 0.0;
    for (int p = beg + lane; p < end; p += 32) {
        int c = g_ccol[p];
        double wv = (c == w) ? 0.0 : (double)g_cw[p];
        deg2 += wv;
        aggr += wv * g_hLd[c];
    }
    deg2 = wsumd(deg2);
    aggr = wsumd(aggr);
    if (lane == 0) {
        double z = deg2 * (g_f1d[w] + (double)b1[0]) + aggr + g_f2d[w] + (double)b2[0];
        g_fitd[w] = 1.0 / (1.0 + exp(-z));
    }
}

// ================= O(N log N) rankings =======================================
__global__ void k_sortd_chunk() {
    __shared__ unsigned long long sk[512];
    __shared__ int si[512];
    int b = blockIdx.x, t = threadIdx.x;
    int base = b * 512;
    sk[t]       = (unsigned long long)__double_as_longlong(g_fitd[base + t]);
    sk[t + 256] = (unsigned long long)__double_as_longlong(g_fitd[base + t + 256]);
    si[t] = base + t;
    si[t + 256] = base + t + 256;
    __syncthreads();
    for (int k = 2; k <= 512; k <<= 1) {
        for (int j = k >> 1; j > 0; j >>= 1) {
            #pragma unroll
            for (int s = 0; s < 2; s++) {
                int i = t + s * 256;
                int ixj = i ^ j;
                if (ixj > i) {
                    unsigned long long a = sk[i], c = sk[ixj];
                    int ia = si[i], ic = si[ixj];
                    bool up = ((i & k) == 0);
                    bool cba = (c > a) || (c == a && ic < ia);
                    bool sw = up ? cba : !cba;
                    if (sw) { sk[i] = c; sk[ixj] = a; si[i] = ic; si[ixj] = ia; }
                }
            }
            __syncthreads();
        }
    }
    g_skd[base + t] = sk[t];
    g_skd[base + t + 256] = sk[t + 256];
    g_sidxd[base + t] = si[t];
    g_sidxd[base + t + 256] = si[t + 256];
}

__global__ void k_rankx() {
    int i = blockIdx.x * blockDim.x + threadIdx.x;
    if (i >= Nn) return;
    unsigned long long ki = (unsigned long long)__double_as_longlong(g_fitd[i]);
    int rk = 0;
    for (int b = 0; b < 16; b++) {
        const unsigned long long* ak = g_skd + b * 512;
        const int* ai = g_sidxd + b * 512;
        int lo = 0, hi = 512;
        while (lo < hi) {
            int mid = (lo + hi) >> 1;
            unsigned long long km = ak[mid];
            bool before = (km > ki) || (km == ki && ai[mid] < i);
            if (before) lo = mid + 1; else hi = mid;
        }
        rk += lo;
    }
    if (rk <= KN) g_permx[rk] = i;
}

__global__ void k_gap() {
    __shared__ double sg[1024];
    __shared__ int si[1024];
    int t = threadIdx.x;
    double best = 1e300; int bi = 0;
    for (int i = t; i < KN; i += 1024) {
        double g = g_fitd[g_permx[i]] - g_fitd[g_permx[i + 1]];
        if (g < best || (g == best && i < bi)) { best = g; bi = i; }
    }
    sg[t] = best; si[t] = bi;
    __syncthreads();
    for (int d = 512; d; d >>= 1) {
        if (t < d) {
            if (sg[t + d] < sg[t] || (sg[t + d] == sg[t] && si[t + d] < si[t])) {
                sg[t] = sg[t + d]; si[t] = si[t + d];
            }
        }
        __syncthreads();
    }
    if (t == 0) { g_pa = g_permx[si[0]]; g_pb = g_permx[si[0] + 1]; }
}

__global__ void k_sorte_chunk() {
    __shared__ unsigned long long sk[512];
    int b = blockIdx.x, t = threadIdx.x;
    int base = b * 512;
    sk[t] = g_keye[base + t];
    sk[t + 256] = g_keye[base + t + 256];
    __syncthreads();
    for (int k = 2; k <= 512; k <<= 1) {
        for (int j = k >> 1; j > 0; j >>= 1) {
            #pragma unroll
            for (int s = 0; s < 2; s++) {
                int i = t + s * 256;
                int ixj = i ^ j;
                if (ixj > i) {
                    unsigned long long a = sk[i], c = sk[ixj];
                    bool up = ((i & k) == 0);
                    bool sw = up ? (a < c) : (a > c);
                    if (sw) { sk[i] = c; sk[ixj] = a; }
                }
            }
            __syncthreads();
        }
    }
    g_skeye[base + t] = sk[t];
    g_skeye[base + t + 256] = sk[t + 256];
}

__global__ void k_ranke2() {
    int i = blockIdx.x * blockDim.x + threadIdx.x;
    if (i >= Nn) return;
    unsigned long long ki = g_keye[i];
    int rk = 0;
    for (int b = 0; b < 16; b++) {
        const unsigned long long* arr = g_skeye + b * 512;
        int lo = 0, hi = 512;
        while (lo < hi) {
            int mid = (lo + hi) >> 1;
            if (arr[mid] > ki) lo = mid + 1; else hi = mid;
        }
        rk += lo;
    }
    g_ranke[i] = rk;
    g_perme[rk] = i;
}

__global__ void k_fix() {
    int a = g_pa, b = g_pb;
    int pa = g_ranke[a], pb = g_ranke[b];
    if (pa > pb) {
        g_perme[pb] = a;
        g_perme[pa] = b;
    }
}

__global__ void k_finalize(float* __restrict__ perm_f) {
    int k = blockIdx.x * blockDim.x + threadIdx.x;
    if (k < KN) {
        int i = g_perme[k];
        g_inp[i] = 1;
        g_nidx[i] = k;
        perm_f[k] = (float)i;
    }
}

__global__ void k_xout(float* __restrict__ xo) {
    int k = blockIdx.x, t = threadIdx.x;
    int i = g_perme[k];
    xo[(size_t)k * Cc + t] = __fmul_rn(g_outf[(size_t)i * Cc + t], g_fitf[i]);
}

// ---------------- S, Emat ---------------------------------------------------
__global__ void k_sval(const int* src, const int* dst, const float* ew,
                       const float* __restrict__ att_out, float* __restrict__ sval_out) {
    int e = blockIdx.x * blockDim.x + threadIdx.x;
    if (e >= ET) return;
    int r, c; float w;
    edge_of(e, src, dst, ew, r, c, w);
    int inp = g_inp[r];
    sval_out[e] = inp ? att_out[e] : 0.0f;
    if (inp) atomicAdd(&g_scnt[c], 1);
}

__global__ void k_sdscat(const int* src, const int* dst, const float* ew,
                         const float* __restrict__ att_out) {
    int e = blockIdx.x * blockDim.x + threadIdx.x;
    if (e >= ET) return;
    int r, c; float w;
    edge_of(e, src, dst, ew, r, c, w);
    if (g_inp[r]) {
        int pos = atomicAdd(&g_scur[c], 1);
        g_sdp[pos] = g_nidx[r];
        g_sdv[pos] = att_out[e];
    }
}

__global__ void k_emat(const int* src, const int* dst, const float* ew,
                       float* __restrict__ emat) {
    int e = blockIdx.x * blockDim.x + threadIdx.x;
    if (e >= ET) return;
    int r, c; float w;
    edge_of(e, src, dst, ew, r, c, w);
    int rb = g_soff[r], re = g_soff[r + 1];
    int cb = g_soff[c], ce = g_soff[c + 1];
    for (int i = rb; i < re; i++) {
        float v1w = g_sdv[i] * w;
        float* rowp = emat + (size_t)g_sdp[i] * KN;
        for (int j = cb; j < ce; j++)
            atomicAdd(&rowp[g_sdp[j]], v1w * g_sdv[j]);
    }
}

__global__ void k_diag(float* __restrict__ emat) {
    int d = blockIdx.x * blockDim.x + threadIdx.x;
    if (d < KN) emat[(size_t)d * KN + d] = 1.0f;
}

// ---------------- launcher --------------------------------------------------
extern "C" void kernel_launch(void* const* d_in, const int* in_sizes, int n_in,
                              void* d_out, int out_size) {
    const float* x     = (const float*)d_in[0];
    const int*   src   = (const int*)d_in[1];
    const int*   dst   = (const int*)d_in[2];
    const float* ew    = (const float*)d_in[3];
    const float* W_gcn = (const float*)d_in[4];
    const float* b_gcn = (const float*)d_in[5];
    const float* Wq    = (const float*)d_in[6];
    const float* bq    = (const float*)d_in[7];
    const float* Wa    = (const float*)d_in[8];
    const float* ba    = (const float*)d_in[9];
    const float* W_le  = (const float*)d_in[10];
    const float* W_le1 = (const float*)d_in[11];
    const float* b_le1 = (const float*)d_in[12];
    const float* W_le2 = (const float*)d_in[13];
    const float* b_le2 = (const float*)d_in[14];

    float* out    = (float*)d_out;
    float* xout_o = out;
    float* emat_o = out + EMAT_OFF;
    float* perm_o = out + PERM_OFF;
    float* sval_o = out + SVAL_OFF;
    float* att_o  = out + ATT_OFF;

    // one extra stream + events, created ONCE (first call = correctness run),
    // reused on the capture call -> no resource churn during/after capture
    static cudaStream_t s2 = nullptr;
    static cudaEvent_t evRoot = nullptr, evCSR = nullptr, evJoin = nullptr,
                       evH = nullptr, evFix = nullptr;
    if (!s2) {
        cudaStreamCreate(&s2);
        cudaEventCreateWithFlags(&evRoot, cudaEventDisableTiming);
        cudaEventCreateWithFlags(&evCSR, cudaEventDisableTiming);
        cudaEventCreateWithFlags(&evJoin, cudaEventDisableTiming);
        cudaEventCreateWithFlags(&evH, cudaEventDisableTiming);
        cudaEventCreateWithFlags(&evFix, cudaEventDisableTiming);
    }

    cudaMemsetAsync(emat_o, 0, (size_t)KN * KN * sizeof(float));
    cudaEventRecord(evRoot, 0);
    cudaStreamWaitEvent(s2, evRoot, 0);

    // s2: CSR-independent GEMMs overlap CSR build
    k_gemm_h<<<Nn, Cc, 0, s2>>>(x, W_gcn);
    cudaEventRecord(evH, s2);
    k_gemm_d<<<Nn / 16, 128, 0, s2>>>(x, W_gcn);
    k_vvec<<<1, 128, 0, s2>>>(Wq, Wa, bq);

    // stream0: CSR build
    k_init<<<32, 256>>>();
    k_cnt<<<Ee / 256, 256>>>(src);
    {
        int* d_cnt; cudaGetSymbolAddress((void**)&d_cnt, g_cnt);
        int* d_off; cudaGetSymbolAddress((void**)&d_off, g_off);
        int* d_cur; cudaGetSymbolAddress((void**)&d_cur, g_cur);
        k_scan<<<1, 1024>>>(d_cnt, d_off, d_cur);
    }
    k_scatter<<<(ET + 255) / 256, 256>>>(src, dst, ew);
    k_sortrow<<<32, 256>>>();
    cudaEventRecord(evCSR, 0);

    // s2: fp64 exact pipeline (after CSR)
    cudaStreamWaitEvent(s2, evCSR, 0);
    k_degs_d<<<32, 256, 0, s2>>>();
    k_xpool_d<<<Nn / 8, 256, 0, s2>>>(b_gcn);
    k_xqa12_d<<<Nn / 8, 256, 0, s2>>>(Wa);
    k_soft_d<<<Nn / 8, 256, 0, s2>>>(ba);
    k_out_d<<<Nn / 8, 256, 0, s2>>>(x);
    k_ledots_d<<<Nn / 8, 256, 0, s2>>>(W_le, W_le1, W_le2);
    k_fit_d<<<Nn / 8, 256, 0, s2>>>(b_le1, b_le2);
    k_sortd_chunk<<<16, 256, 0, s2>>>();
    k_rankx<<<32, 256, 0, s2>>>();
    k_gap<<<1, 1024, 0, s2>>>();
    cudaEventRecord(evJoin, s2);

    // stream0: fp32 emulation pipeline (concurrent with s2)
    k_deg<<<32, 256>>>();
    k_nrm<<<(ET + 255) / 256, 256>>>();
    cudaStreamWaitEvent(0, evH, 0);             // g_h ready
    k_xpool<<<Nn, Cc>>>(b_gcn);
    k_xqmq<<<Nn, Cc>>>(Wq, bq, Wa);
    k_s<<<(ET + 255) / 256, 256>>>(Wa, ba);
    k_soft<<<32, 256>>>(att_o);
    k_out<<<Nn, Cc>>>(x);
    k_hl<<<32, 256>>>(W_le, W_le1, b_le1, W_le2, b_le2);
    k_fit<<<32, 256>>>();
    k_sorte_chunk<<<16, 256>>>();
    k_ranke2<<<32, 256>>>();

    // join + finalize
    cudaStreamWaitEvent(0, evJoin, 0);
    k_fix<<<1, 1>>>();
    k_finalize<<<KN / 256, 256>>>(perm_o);
    cudaEventRecord(evFix, 0);

    // s2: xout overlaps the S/Emat tail
    cudaStreamWaitEvent(s2, evFix, 0);
    k_xout<<<KN, Cc, 0, s2>>>(xout_o);
    cudaEventRecord(evJoin, s2);

    // stream0: S, Emat
    k_sval<<<(ET + 255) / 256, 256>>>(src, dst, ew, att_o, sval_o);
    {
        int* d_scnt; cudaGetSymbolAddress((void**)&d_scnt, g_scnt);
        int* d_soff; cudaGetSymbolAddress((void**)&d_soff, g_soff);
        int* d_scur; cudaGetSymbolAddress((void**)&d_scur, g_scur);
        k_scan<<<1, 1024>>>(d_scnt, d_soff, d_scur);
    }
    k_sdscat<<<(ET + 255) / 256, 256>>>(src, dst, ew, att_o);
    k_emat<<<(ET + 255) / 256, 256>>>(src, dst, ew, emat_o);
    k_diag<<<KN / 256, 256>>>(emat_o);

    // final join so all forked work lands back on the origin stream
    cudaStreamWaitEvent(0, evJoin, 0);
}

// round 17
// speedup vs baseline: 1.4115x; 1.0109x over previous
#include <cuda_runtime.h>
#include <math.h>

#define Nn 8192
#define Cc 128
#define Ee 131072
#define ET (Ee + Nn)
#define KN 2048

#define EMAT_OFF (KN*Cc)
#define PERM_OFF (EMAT_OFF + KN*KN)
#define SVAL_OFF (PERM_OFF + KN)
#define ATT_OFF  (SVAL_OFF + ET)

// ---------------- shared CSR ------------------------------------------------
__device__ int   g_cnt[Nn], g_off[Nn+1], g_cur[Nn];
__device__ int   g_scnt[Nn], g_soff[Nn+1], g_scur[Nn];
__device__ int   g_eid[ET], g_ccol[ET], g_prow[ET];
__device__ float g_cw[ET];
__device__ int   g_inp[Nn], g_nidx[Nn];
__device__ int   g_sdp[ET];
__device__ float g_sdv[ET];

// ---------------- fp32 (emulation) buffers ----------------------------------
__device__ float g_h[Nn*Cc], g_xpool[Nn*Cc], g_outf[Nn*Cc];
__device__ float g_dinv[Nn], g_a1l[Nn*4];
__device__ float g_hL[Nn], g_f1b[Nn], g_f2b[Nn], g_fitf[Nn];
__device__ float g_s[ET], g_att[ET];

// ---------------- fp64 (exact) buffers --------------------------------------
__device__ double g_hd[Nn*Cc], g_xpd[Nn*Cc];
__device__ double g_dinvd[Nn], g_a1d[Nn], g_a2d[Nn], g_hLd[Nn], g_f1d[Nn], g_f2d[Nn];
__device__ double g_vd[Cc], g_b0d;
__device__ double g_sbufd[ET], g_attd[ET];
__device__ double g_fitd[Nn];

// ---------------- rankings --------------------------------------------------
__device__ int   g_ranke[Nn];
__device__ int   g_permx[KN+1];
__device__ int   g_perme[Nn];
__device__ unsigned long long g_keye[Nn];
__device__ unsigned long long g_skeye[Nn];
__device__ unsigned long long g_skd[Nn];
__device__ int   g_sidxd[Nn];
__device__ int   g_pa, g_pb;

// ---------------- helpers ---------------------------------------------------
__device__ __forceinline__ void edge_of(int e, const int* src, const int* dst,
                                        const float* ew, int& r, int& c, float& w) {
    if (e < Ee) { r = src[e]; c = dst[e]; w = ew[e]; }
    else        { r = e - Ee; c = r;      w = 1.0f;  }
}
__device__ __forceinline__ double wsumd(double v) {
    #pragma unroll
    for (int o = 16; o; o >>= 1) v += __shfl_xor_sync(0xffffffffu, v, o);
    return v;
}
__device__ __forceinline__ void acc2(float& s, float& c, float a, float b) {
    float p = __fmul_rn(a, b);
    float e = __fmaf_rn(a, b, -p);
    float t = s + p;
    float comp = (fabsf(s) >= fabsf(p)) ? ((s - t) + p) : ((p - t) + s);
    s = t;
    c = c + comp + e;
}
// XLA CPU VF32Exp (verbatim)
__device__ __forceinline__ float xla_expf(float x) {
    float v = fminf(fmaxf(x, -87.8f), 88.8f);
    float zm = __fmaf_rn(v, 1.44269504088896340736f, 12582912.0f);
    float k = __fadd_rn(zm, -12582912.0f);
    float r = __fmaf_rn(k, -0.693145751953125f, v);
    r = __fmaf_rn(k, -1.42860677e-6f, r);
    float p = 0.00828929059f;
    p = __fmaf_rn(p, r, 0.0418978221f);
    p = __fmaf_rn(p, r, 0.166676521f);
    p = __fmaf_rn(p, r, 0.5f);
    p = __fmaf_rn(p, r, 1.0f);
    p = __fmaf_rn(p, r, 1.0f);
    int ik = (int)k;
    return __uint_as_float(__float_as_uint(p) + ((unsigned int)ik << 23));
}
// XLA tanh rational approx (verbatim)
__device__ __forceinline__ float xla_tanh(float x) {
    const float kClamp = 7.90531110763549805f;
    float xc = fminf(fmaxf(x, -kClamp), kClamp);
    float x2 = __fmul_rn(xc, xc);
    float p = -2.76076847742355e-16f;
    p = __fmaf_rn(p, x2, 2.00018790482477e-13f);
    p = __fmaf_rn(p, x2, -8.60467152213735e-11f);
    p = __fmaf_rn(p, x2, 5.12229709037114e-08f);
    p = __fmaf_rn(p, x2, 1.48572235717979e-05f);
    p = __fmaf_rn(p, x2, 6.37261928875436e-04f);
    p = __fmaf_rn(p, x2, 4.89352455891786e-03f);
    float num = __fmul_rn(xc, p);
    float q = 1.19825839466702e-06f;
    q = __fmaf_rn(q, x2, 1.18534705686654e-04f);
    q = __fmaf_rn(q, x2, 2.26843463243900e-03f);
    q = __fmaf_rn(q, x2, 4.89352518554385e-03f);
    float r = __fdiv_rn(num, q);
    return (fabsf(x) < 0.0004f) ? x : r;
}
__device__ __forceinline__ float xla_sigmoid(float z) {
    float t = xla_tanh(__fmul_rn(0.5f, z));
    return __fadd_rn(0.5f, __fmul_rn(0.5f, t));
}

// ---------------- CSR build -------------------------------------------------
__global__ void k_init() {
    int i = blockIdx.x * blockDim.x + threadIdx.x;
    if (i < Nn) {
        g_cnt[i] = 1;
        g_scnt[i] = 0;
        g_inp[i] = 0;
        g_nidx[i] = 0;
    }
}

__global__ void k_cnt(const int* src) {
    int e = blockIdx.x * blockDim.x + threadIdx.x;
    if (e < Ee) atomicAdd(&g_cnt[src[e]], 1);
}

__global__ void k_scan(const int* cnt, int* off, int* cur) {
    __shared__ int part[1024];
    int t = threadIdx.x;
    int base = t * 8;
    int local[8];
    int s = 0;
    #pragma unroll
    for (int i = 0; i < 8; i++) { local[i] = s; s += cnt[base + i]; }
    part[t] = s;
    __syncthreads();
    for (int d = 1; d < 1024; d <<= 1) {
        int v = (t >= d) ? part[t - d] : 0;
        __syncthreads();
        part[t] += v;
        __syncthreads();
    }
    int add = (t > 0) ? part[t - 1] : 0;
    #pragma unroll
    for (int i = 0; i < 8; i++) {
        int o = add + local[i];
        off[base + i] = o;
        cur[base + i] = o;
    }
    if (t == 1023) off[Nn] = part[1023];
}

__global__ void k_scatter(const int* src, const int* dst, const float* ew) {
    int e = blockIdx.x * blockDim.x + threadIdx.x;
    if (e >= ET) return;
    int r, c; float w;
    edge_of(e, src, dst, ew, r, c, w);
    int pos = atomicAdd(&g_cur[r], 1);
    g_eid[pos] = e;
    g_ccol[pos] = c;
    g_cw[pos] = w;
    g_prow[pos] = r;
}

__global__ void k_sortrow() {
    int r = blockIdx.x * blockDim.x + threadIdx.x;
    if (r >= Nn) return;
    int beg = g_off[r], end = g_off[r + 1];
    for (int i = beg + 1; i < end; i++) {
        int ke = g_eid[i]; int kc = g_ccol[i]; float kw = g_cw[i];
        int j = i - 1;
        while (j >= beg && g_eid[j] > ke) {
            g_eid[j + 1] = g_eid[j]; g_ccol[j + 1] = g_ccol[j]; g_cw[j + 1] = g_cw[j];
            j--;
        }
        g_eid[j + 1] = ke; g_ccol[j + 1] = kc; g_cw[j + 1] = kw;
    }
}

// ================= fp32 pipeline (bit-exact emulation) ======================
__global__ void k_deg() {
    int r = blockIdx.x * blockDim.x + threadIdx.x;
    if (r >= Nn) return;
    int beg = g_off[r], end = g_off[r + 1];
    float d = 0.0f;
    for (int p = beg; p < end; p++) d = __fadd_rn(d, g_cw[p]);
    g_dinv[r] = (d > 0.0f) ? __fdiv_rn(1.0f, __fsqrt_rn(d)) : 0.0f;
}

__global__ void k_gemm_h(const float* __restrict__ X, const float* __restrict__ W) {
    __shared__ float xs[Cc];
    int i = blockIdx.x, j = threadIdx.x;
    xs[j] = X[(size_t)i * Cc + j];
    __syncthreads();
    float acc = 0.0f;
    for (int k = 0; k < Cc; k++)
        acc = __fmaf_rn(xs[k], W[k * Cc + j], acc);
    g_h[(size_t)i * Cc + j] = acc;
}

#define CHUNK 128
// xpool with inline nrm (same __fmul_rn chain as the old k_nrm)
__global__ void k_xpool(const float* __restrict__ bg) {
    __shared__ int sc[CHUNK];
    __shared__ float sn[CHUNK];
    int r = blockIdx.x, t = threadIdx.x;
    int beg = g_off[r], end = g_off[r + 1];
    float dr = g_dinv[r];
    float acc = 0.0f;
    for (int base = beg; base < end; base += CHUNK) {
        int m = min(CHUNK, end - base);
        if (t < m) {
            int c = g_ccol[base + t];
            sc[t] = c;
            sn[t] = __fmul_rn(__fmul_rn(dr, g_cw[base + t]), g_dinv[c]);
        }
        __syncthreads();
        for (int i = 0; i < m; i++)
            acc = __fadd_rn(acc, __fmul_rn(sn[i], g_h[(size_t)sc[i] * Cc + t]));
        __syncthreads();
    }
    acc = __fadd_rn(acc, bg[t]);
    g_xpool[(size_t)r * Cc + t] = acc;
}

// fused: xq row -> mq row -> a1 lane partials (bit-exact chains)
__global__ void k_xqmq(const float* __restrict__ Wq, const float* __restrict__ bq,
                       const float* __restrict__ Wa) {
    __shared__ int sc[CHUNK];
    __shared__ float xqs[Cc];
    __shared__ float mqs[Cc];
    int r = blockIdx.x, t = threadIdx.x;
    int beg = g_off[r], end = g_off[r + 1];
    float acc = -INFINITY;
    for (int base = beg; base < end; base += CHUNK) {
        int m = min(CHUNK, end - base);
        if (t < m) sc[t] = g_ccol[base + t];
        __syncthreads();
        for (int i = 0; i < m; i++)
            acc = fmaxf(acc, g_xpool[(size_t)sc[i] * Cc + t]);
        __syncthreads();
    }
    xqs[t] = acc;
    __syncthreads();
    float mv = 0.0f;
    for (int k = 0; k < Cc; k++)
        mv = __fmaf_rn(xqs[k], Wq[k * Cc + t], mv);
    mqs[t] = __fadd_rn(mv, bq[t]);
    __syncthreads();
    if (t < 4) {
        float l = 0.0f;
        for (int i = 0; i < 32; i++)
            l = __fmaf_rn(mqs[i * 4 + t], Wa[i * 4 + t], l);
        g_a1l[r * 4 + t] = l;
    }
}

__global__ void k_s(const float* __restrict__ Wa, const float* __restrict__ ba) {
    __shared__ float4 wa2[32];
    if (threadIdx.x < 32)
        wa2[threadIdx.x] = *(const float4*)(Wa + Cc + threadIdx.x * 4);
    __syncthreads();
    int p = blockIdx.x * blockDim.x + threadIdx.x;
    if (p >= ET) return;
    const float4* xp = (const float4*)&g_xpool[(size_t)g_ccol[p] * Cc];
    int r = g_prow[p];
    float l0 = g_a1l[r * 4 + 0], l1 = g_a1l[r * 4 + 1];
    float l2 = g_a1l[r * 4 + 2], l3 = g_a1l[r * 4 + 3];
    #pragma unroll 8
    for (int i = 0; i < 32; i++) {
        float4 v = xp[i];
        float4 w = wa2[i];
        l0 = __fmaf_rn(v.x, w.x, l0);
        l1 = __fmaf_rn(v.y, w.y, l1);
        l2 = __fmaf_rn(v.z, w.z, l2);
        l3 = __fmaf_rn(v.w, w.w, l3);
    }
    float acc = __fadd_rn(__fadd_rn(l0, l2), __fadd_rn(l1, l3));
    acc = __fadd_rn(acc, ba[0]);
    g_s[p] = (acc >= 0.0f) ? acc : __fmul_rn(0.2f, acc);
}

// warp-per-row softmax: max order-free (exact), exp parallel,
// SUM sequential in eid order by lane 0 (value-identical to serial version)
__global__ void k_soft(float* __restrict__ att_out) {
    int w = (blockIdx.x * blockDim.x + threadIdx.x) >> 5;
    if (w >= Nn) return;
    int lane = threadIdx.x & 31;
    int beg = g_off[w], end = g_off[w + 1];
    float m = -INFINITY;
    for (int p = beg + lane; p < end; p += 32) m = fmaxf(m, g_s[p]);
    #pragma unroll
    for (int o = 16; o; o >>= 1) m = fmaxf(m, __shfl_xor_sync(0xffffffffu, m, o));
    for (int p = beg + lane; p < end; p += 32)
        g_att[p] = xla_expf(__fadd_rn(g_s[p], -m));
    __syncwarp();
    float den = 0.0f;
    if (lane == 0) {
        float sum = 0.0f;
        for (int p = beg; p < end; p++) sum = __fadd_rn(sum, g_att[p]);
        den = __fadd_rn(sum, 1e-16f);
    }
    den = __shfl_sync(0xffffffffu, den, 0);
    for (int p = beg + lane; p < end; p += 32) {
        float a = __fdiv_rn(g_att[p], den);
        g_att[p] = a;
        att_out[g_eid[p]] = a;
    }
}

// fused: out row gather + hL/f1b/f2b dots (bit-exact chains)
__global__ void k_outhl(const float* __restrict__ x,
                        const float* __restrict__ Wle, const float* __restrict__ Wle1,
                        const float* __restrict__ b1, const float* __restrict__ Wle2,
                        const float* __restrict__ b2) {
    __shared__ int sc[CHUNK];
    __shared__ float sa[CHUNK];
    __shared__ float outs[Cc];
    int r = blockIdx.x, t = threadIdx.x;
    int beg = g_off[r], end = g_off[r + 1];
    float acc = 0.0f;
    for (int base = beg; base < end; base += CHUNK) {
        int m = min(CHUNK, end - base);
        if (t < m) { sc[t] = g_ccol[base + t]; sa[t] = g_att[base + t]; }
        __syncthreads();
        for (int i = 0; i < m; i++)
            acc = __fadd_rn(acc, __fmul_rn(sa[i], x[(size_t)sc[i] * Cc + t]));
        __syncthreads();
    }
    g_outf[(size_t)r * Cc + t] = acc;
    outs[t] = acc;
    __syncthreads();
    if (t < 3) {
        const float* W = (t == 0) ? Wle : (t == 1) ? Wle1 : Wle2;
        float l0 = 0, l1 = 0, l2 = 0, l3 = 0;
        for (int i = 0; i < 32; i++) {
            l0 = __fmaf_rn(outs[i * 4 + 0], W[i * 4 + 0], l0);
            l1 = __fmaf_rn(outs[i * 4 + 1], W[i * 4 + 1], l1);
            l2 = __fmaf_rn(outs[i * 4 + 2], W[i * 4 + 2], l2);
            l3 = __fmaf_rn(outs[i * 4 + 3], W[i * 4 + 3], l3);
        }
        float res = __fadd_rn(__fadd_rn(l0, l2), __fadd_rn(l1, l3));
        if (t == 0) g_hL[r] = res;
        else if (t == 1) g_f1b[r] = __fadd_rn(res, b1[0]);
        else g_f2b[r] = __fadd_rn(res, b2[0]);
    }
}

__global__ void k_fit() {
    int r = blockIdx.x * blockDim.x + threadIdx.x;
    if (r >= Nn) return;
    int beg = g_off[r], end = g_off[r + 1];
    float deg2 = 0.0f, aggr = 0.0f;
    for (int p = beg; p < end; p++) {
        int c = g_ccol[p];
        float wle = (c == r) ? 0.0f : g_cw[p];
        deg2 = __fadd_rn(deg2, wle);
        aggr = __fadd_rn(aggr, __fmul_rn(wle, g_hL[c]));
    }
    float z = __fadd_rn(__fadd_rn(__fmul_rn(deg2, g_f1b[r]), aggr), g_f2b[r]);
    float f = xla_sigmoid(z);
    g_fitf[r] = f;
    g_keye[r] = ((unsigned long long)__float_as_uint(f) << 13)
              | (unsigned int)(Nn - 1 - r);
}

// ================= fp64 exact pipeline =======================================
__global__ void k_degs_d() {
    int r = blockIdx.x * blockDim.x + threadIdx.x;
    if (r >= Nn) return;
    int beg = g_off[r], end = g_off[r + 1];
    double s = 0.0;
    for (int p = beg; p < end; p++) s += (double)g_cw[p];
    g_dinvd[r] = (s > 0.0) ? 1.0 / sqrt(s) : 0.0;
}

__global__ void k_gemm_d(const float* __restrict__ X, const float* __restrict__ W) {
    __shared__ float xs[16][Cc];
    int col = threadIdx.x;
    int row0 = blockIdx.x * 16;
    for (int i = threadIdx.x; i < 16 * Cc; i += 128)
        xs[i >> 7][i & 127] = X[(row0 + (i >> 7)) * Cc + (i & 127)];
    __syncthreads();
    float s[16], cc[16];
    #pragma unroll
    for (int i = 0; i < 16; i++) { s[i] = 0.0f; cc[i] = 0.0f; }
    for (int k = 0; k < Cc; k++) {
        float wv = W[k * Cc + col];
        #pragma unroll
        for (int i = 0; i < 16; i++) acc2(s[i], cc[i], xs[i][k], wv);
    }
    #pragma unroll
    for (int i = 0; i < 16; i++)
        g_hd[(size_t)(row0 + i) * Cc + col] = (double)s[i] + (double)cc[i];
}

__global__ void k_xpool_d(const float* __restrict__ bg) {
    int w = (blockIdx.x * blockDim.x + threadIdx.x) >> 5;
    if (w >= Nn) return;
    int lane = threadIdx.x & 31;
    int beg = g_off[w], end = g_off[w + 1];
    double dr = g_dinvd[w];
    double a0 = (double)bg[lane * 4 + 0], a1 = (double)bg[lane * 4 + 1];
    double a2 = (double)bg[lane * 4 + 2], a3 = (double)bg[lane * 4 + 3];
    for (int p = beg; p < end; p++) {
        int c = g_ccol[p];
        double nrm = dr * (double)g_cw[p] * g_dinvd[c];
        const double* hr = &g_hd[(size_t)c * Cc + lane * 4];
        a0 += nrm * hr[0]; a1 += nrm * hr[1];
        a2 += nrm * hr[2]; a3 += nrm * hr[3];
    }
    double* xr = &g_xpd[(size_t)w * Cc + lane * 4];
    xr[0] = a0; xr[1] = a1; xr[2] = a2; xr[3] = a3;
}

__global__ void k_vvec(const float* __restrict__ Wq, const float* __restrict__ Wa,
                       const float* __restrict__ bq) {
    int c = threadIdx.x;
    double s = 0.0;
    for (int k = 0; k < Cc; k++) s += (double)Wq[c * Cc + k] * (double)Wa[k];
    g_vd[c] = s;
    if (c == 0) {
        double b = 0.0;
        for (int k = 0; k < Cc; k++) b += (double)bq[k] * (double)Wa[k];
        g_b0d = b;
    }
}

// fused: xq_d gather + a12_d (identical arithmetic)
__global__ void k_xqa12_d(const float* __restrict__ Wa) {
    int w = (blockIdx.x * blockDim.x + threadIdx.x) >> 5;
    if (w >= Nn) return;
    int lane = threadIdx.x & 31;
    int beg = g_off[w], end = g_off[w + 1];
    double a0 = -INFINITY, a1 = -INFINITY, a2 = -INFINITY, a3 = -INFINITY;
    for (int p = beg; p < end; p++) {
        int c = g_ccol[p];
        const double* hr = &g_xpd[(size_t)c * Cc + lane * 4];
        a0 = fmax(a0, hr[0]); a1 = fmax(a1, hr[1]);
        a2 = fmax(a2, hr[2]); a3 = fmax(a3, hr[3]);
    }
    const double* vq = &g_vd[lane * 4];
    const double* xp = &g_xpd[(size_t)w * Cc + lane * 4];
    double s1 = a0*vq[0] + a1*vq[1] + a2*vq[2] + a3*vq[3];
    double s2 = xp[0]*(double)Wa[Cc+lane*4+0] + xp[1]*(double)Wa[Cc+lane*4+1]
              + xp[2]*(double)Wa[Cc+lane*4+2] + xp[3]*(double)Wa[Cc+lane*4+3];
    s1 = wsumd(s1);
    s2 = wsumd(s2);
    if (lane == 0) { g_a1d[w] = s1 + g_b0d; g_a2d[w] = s2; }
}

__global__ void k_soft_d(const float* __restrict__ ba) {
    int w = (blockIdx.x * blockDim.x + threadIdx.x) >> 5;
    if (w >= Nn) return;
    int lane = threadIdx.x & 31;
    int beg = g_off[w], end = g_off[w + 1];
    double a1r = g_a1d[w];
    double ba0 = (double)ba[0];
    double mx = -INFINITY;
    for (int p = beg + lane; p < end; p += 32) {
        double s = a1r + g_a2d[g_ccol[p]] + ba0;
        s = (s >= 0.0) ? s : 0.2 * s;
        g_sbufd[p] = s;
        mx = fmax(mx, s);
    }
    #pragma unroll
    for (int o = 16; o; o >>= 1) mx = fmax(mx, __shfl_xor_sync(0xffffffffu, mx, o));
    double sum = 0.0;
    for (int p = beg + lane; p < end; p += 32) {
        double e = exp(g_sbufd[p] - mx);
        g_sbufd[p] = e;
        sum += e;
    }
    sum = wsumd(sum);
    double den = sum + 1e-16;
    for (int p = beg + lane; p < end; p += 32)
        g_attd[p] = g_sbufd[p] / den;
}

// fused: out_d row (registers) + ledots_d (identical add order; g_outd deleted)
__global__ void k_outled_d(const float* __restrict__ x,
                           const float* __restrict__ Wle, const float* __restrict__ Wle1,
                           const float* __restrict__ Wle2) {
    int w = (blockIdx.x * blockDim.x + threadIdx.x) >> 5;
    if (w >= Nn) return;
    int lane = threadIdx.x & 31;
    int beg = g_off[w], end = g_off[w + 1];
    double a0 = 0, a1 = 0, a2 = 0, a3 = 0;
    for (int p = beg; p < end; p++) {
        int c = g_ccol[p];
        double a = g_attd[p];
        float4 xv = *(const float4*)&x[(size_t)c * Cc + lane * 4];
        a0 += a * (double)xv.x; a1 += a * (double)xv.y;
        a2 += a * (double)xv.z; a3 += a * (double)xv.w;
    }
    double s0 = 0, s1 = 0, s2 = 0;
    s0 += a0 * (double)Wle [lane * 4 + 0];
    s0 += a1 * (double)Wle [lane * 4 + 1];
    s0 += a2 * (double)Wle [lane * 4 + 2];
    s0 += a3 * (double)Wle [lane * 4 + 3];
    s1 += a0 * (double)Wle1[lane * 4 + 0];
    s1 += a1 * (double)Wle1[lane * 4 + 1];
    s1 += a2 * (double)Wle1[lane * 4 + 2];
    s1 += a3 * (double)Wle1[lane * 4 + 3];
    s2 += a0 * (double)Wle2[lane * 4 + 0];
    s2 += a1 * (double)Wle2[lane * 4 + 1];
    s2 += a2 * (double)Wle2[lane * 4 + 2];
    s2 += a3 * (double)Wle2[lane * 4 + 3];
    s0 = wsumd(s0); s1 = wsumd(s1); s2 = wsumd(s2);
    if (lane == 0) { g_hLd[w] = s0; g_f1d[w] = s1; g_f2d[w] = s2; }
}

__global__ void k_fit_d(const float* __restrict__ b1, const float* __restrict__ b2) {
    int w = (blockIdx.x * blockDim.x + threadIdx.x) >> 5;
    if (w >= Nn) return;
    int lane = threadIdx.x & 31;
    int beg = g_off[w], end = g_off[w + 1];
    double deg2 = 0.0, aggr = 0.0;
    for (int p = beg + lane; p < end; p += 32) {
        int c = g_ccol[p];
        double wv = (c == w) ? 0.0 : (double)g_cw[p];
        deg2 += wv;
        aggr += wv * g_hLd[c];
    }
    deg2 = wsumd(deg2);
    aggr = wsumd(aggr);
    if (lane == 0) {
        double z = deg2 * (g_f1d[w] + (double)b1[0]) + aggr + g_f2d[w] + (double)b2[0];
        g_fitd[w] = 1.0 / (1.0 + exp(-z));
    }
}

// ================= O(N log N) rankings =======================================
__global__ void k_sortd_chunk() {
    __shared__ unsigned long long sk[512];
    __shared__ int si[512];
    int b = blockIdx.x, t = threadIdx.x;
    int base = b * 512;
    sk[t]       = (unsigned long long)__double_as_longlong(g_fitd[base + t]);
    sk[t + 256] = (unsigned long long)__double_as_longlong(g_fitd[base + t + 256]);
    si[t] = base + t;
    si[t + 256] = base + t + 256;
    __syncthreads();
    for (int k = 2; k <= 512; k <<= 1) {
        for (int j = k >> 1; j > 0; j >>= 1) {
            #pragma unroll
            for (int s = 0; s < 2; s++) {
                int i = t + s * 256;
                int ixj = i ^ j;
                if (ixj > i) {
                    unsigned long long a = sk[i], c = sk[ixj];
                    int ia = si[i], ic = si[ixj];
                    bool up = ((i & k) == 0);
                    bool cba = (c > a) || (c == a && ic < ia);
                    bool sw = up ? cba : !cba;
                    if (sw) { sk[i] = c; sk[ixj] = a; si[i] = ic; si[ixj] = ia; }
                }
            }
            __syncthreads();
        }
    }
    g_skd[base + t] = sk[t];
    g_skd[base + t + 256] = sk[t + 256];
    g_sidxd[base + t] = si[t];
    g_sidxd[base + t + 256] = si[t + 256];
}

__global__ void k_rankx() {
    int i = blockIdx.x * blockDim.x + threadIdx.x;
    if (i >= Nn) return;
    unsigned long long ki = (unsigned long long)__double_as_longlong(g_fitd[i]);
    int rk = 0;
    for (int b = 0; b < 16; b++) {
        const unsigned long long* ak = g_skd + b * 512;
        const int* ai = g_sidxd + b * 512;
        int lo = 0, hi = 512;
        while (lo < hi) {
            int mid = (lo + hi) >> 1;
            unsigned long long km = ak[mid];
            bool before = (km > ki) || (km == ki && ai[mid] < i);
            if (before) lo = mid + 1; else hi = mid;
        }
        rk += lo;
    }
    if (rk <= KN) g_permx[rk] = i;
}

__global__ void k_gap() {
    __shared__ double sg[1024];
    __shared__ int si[1024];
    int t = threadIdx.x;
    double best = 1e300; int bi = 0;
    for (int i = t; i < KN; i += 1024) {
        double g = g_fitd[g_permx[i]] - g_fitd[g_permx[i + 1]];
        if (g < best || (g == best && i < bi)) { best = g; bi = i; }
    }
    sg[t] = best; si[t] = bi;
    __syncthreads();
    for (int d = 512; d; d >>= 1) {
        if (t < d) {
            if (sg[t + d] < sg[t] || (sg[t + d] == sg[t] && si[t + d] < si[t])) {
                sg[t] = sg[t + d]; si[t] = si[t + d];
            }
        }
        __syncthreads();
    }
    if (t == 0) { g_pa = g_permx[si[0]]; g_pb = g_permx[si[0] + 1]; }
}

__global__ void k_sorte_chunk() {
    __shared__ unsigned long long sk[512];
    int b = blockIdx.x, t = threadIdx.x;
    int base = b * 512;
    sk[t] = g_keye[base + t];
    sk[t + 256] = g_keye[base + t + 256];
    __syncthreads();
    for (int k = 2; k <= 512; k <<= 1) {
        for (int j = k >> 1; j > 0; j >>= 1) {
            #pragma unroll
            for (int s = 0; s < 2; s++) {
                int i = t + s * 256;
                int ixj = i ^ j;
                if (ixj > i) {
                    unsigned long long a = sk[i], c = sk[ixj];
                    bool up = ((i & k) == 0);
                    bool sw = up ? (a < c) : (a > c);
                    if (sw) { sk[i] = c; sk[ixj] = a; }
                }
            }
            __syncthreads();
        }
    }
    g_skeye[base + t] = sk[t];
    g_skeye[base + t + 256] = sk[t + 256];
}

__global__ void k_ranke2() {
    int i = blockIdx.x * blockDim.x + threadIdx.x;
    if (i >= Nn) return;
    unsigned long long ki = g_keye[i];
    int rk = 0;
    for (int b = 0; b < 16; b++) {
        const unsigned long long* arr = g_skeye + b * 512;
        int lo = 0, hi = 512;
        while (lo < hi) {
            int mid = (lo + hi) >> 1;
            if (arr[mid] > ki) lo = mid + 1; else hi = mid;
        }
        rk += lo;
    }
    g_ranke[i] = rk;
    g_perme[rk] = i;
}

__global__ void k_fix() {
    int a = g_pa, b = g_pb;
    int pa = g_ranke[a], pb = g_ranke[b];
    if (pa > pb) {
        g_perme[pb] = a;
        g_perme[pa] = b;
    }
}

__global__ void k_finalize(float* __restrict__ perm_f) {
    int k = blockIdx.x * blockDim.x + threadIdx.x;
    if (k < KN) {
        int i = g_perme[k];
        g_inp[i] = 1;
        g_nidx[i] = k;
        perm_f[k] = (float)i;
    }
}

__global__ void k_xout(float* __restrict__ xo) {
    int k = blockIdx.x, t = threadIdx.x;
    int i = g_perme[k];
    xo[(size_t)k * Cc + t] = __fmul_rn(g_outf[(size_t)i * Cc + t], g_fitf[i]);
}

// ---------------- S, Emat ---------------------------------------------------
__global__ void k_sval(const int* src, const int* dst, const float* ew,
                       const float* __restrict__ att_out, float* __restrict__ sval_out) {
    int e = blockIdx.x * blockDim.x + threadIdx.x;
    if (e >= ET) return;
    int r, c; float w;
    edge_of(e, src, dst, ew, r, c, w);
    int inp = g_inp[r];
    sval_out[e] = inp ? att_out[e] : 0.0f;
    if (inp) atomicAdd(&g_scnt[c], 1);
}

__global__ void k_sdscat(const int* src, const int* dst, const float* ew,
                         const float* __restrict__ att_out) {
    int e = blockIdx.x * blockDim.x + threadIdx.x;
    if (e >= ET) return;
    int r, c; float w;
    edge_of(e, src, dst, ew, r, c, w);
    if (g_inp[r]) {
        int pos = atomicAdd(&g_scur[c], 1);
        g_sdp[pos] = g_nidx[r];
        g_sdv[pos] = att_out[e];
    }
}

__global__ void k_emat(const int* src, const int* dst, const float* ew,
                       float* __restrict__ emat) {
    int e = blockIdx.x * blockDim.x + threadIdx.x;
    if (e >= ET) return;
    int r, c; float w;
    edge_of(e, src, dst, ew, r, c, w);
    int rb = g_soff[r], re = g_soff[r + 1];
    int cb = g_soff[c], ce = g_soff[c + 1];
    for (int i = rb; i < re; i++) {
        float v1w = g_sdv[i] * w;
        float* rowp = emat + (size_t)g_sdp[i] * KN;
        for (int j = cb; j < ce; j++)
            atomicAdd(&rowp[g_sdp[j]], v1w * g_sdv[j]);
    }
}

__global__ void k_diag(float* __restrict__ emat) {
    int d = blockIdx.x * blockDim.x + threadIdx.x;
    if (d < KN) emat[(size_t)d * KN + d] = 1.0f;
}

// ---------------- launcher --------------------------------------------------
extern "C" void kernel_launch(void* const* d_in, const int* in_sizes, int n_in,
                              void* d_out, int out_size) {
    const float* x     = (const float*)d_in[0];
    const int*   src   = (const int*)d_in[1];
    const int*   dst   = (const int*)d_in[2];
    const float* ew    = (const float*)d_in[3];
    const float* W_gcn = (const float*)d_in[4];
    const float* b_gcn = (const float*)d_in[5];
    const float* Wq    = (const float*)d_in[6];
    const float* bq    = (const float*)d_in[7];
    const float* Wa    = (const float*)d_in[8];
    const float* ba    = (const float*)d_in[9];
    const float* W_le  = (const float*)d_in[10];
    const float* W_le1 = (const float*)d_in[11];
    const float* b_le1 = (const float*)d_in[12];
    const float* W_le2 = (const float*)d_in[13];
    const float* b_le2 = (const float*)d_in[14];

    float* out    = (float*)d_out;
    float* xout_o = out;
    float* emat_o = out + EMAT_OFF;
    float* perm_o = out + PERM_OFF;
    float* sval_o = out + SVAL_OFF;
    float* att_o  = out + ATT_OFF;

    static cudaStream_t s2 = nullptr;
    static cudaEvent_t evRoot = nullptr, evCSR = nullptr, evJoin = nullptr,
                       evH = nullptr, evFix = nullptr;
    if (!s2) {
        cudaStreamCreate(&s2);
        cudaEventCreateWithFlags(&evRoot, cudaEventDisableTiming);
        cudaEventCreateWithFlags(&evCSR, cudaEventDisableTiming);
        cudaEventCreateWithFlags(&evJoin, cudaEventDisableTiming);
        cudaEventCreateWithFlags(&evH, cudaEventDisableTiming);
        cudaEventCreateWithFlags(&evFix, cudaEventDisableTiming);
    }

    cudaMemsetAsync(emat_o, 0, (size_t)KN * KN * sizeof(float));
    cudaEventRecord(evRoot, 0);
    cudaStreamWaitEvent(s2, evRoot, 0);

    // s2: CSR-independent GEMMs overlap CSR build
    k_gemm_h<<<Nn, Cc, 0, s2>>>(x, W_gcn);
    cudaEventRecord(evH, s2);
    k_gemm_d<<<Nn / 16, 128, 0, s2>>>(x, W_gcn);
    k_vvec<<<1, 128, 0, s2>>>(Wq, Wa, bq);

    // stream0: CSR build
    k_init<<<32, 256>>>();
    k_cnt<<<Ee / 256, 256>>>(src);
    {
        int* d_cnt; cudaGetSymbolAddress((void**)&d_cnt, g_cnt);
        int* d_off; cudaGetSymbolAddress((void**)&d_off, g_off);
        int* d_cur; cudaGetSymbolAddress((void**)&d_cur, g_cur);
        k_scan<<<1, 1024>>>(d_cnt, d_off, d_cur);
    }
    k_scatter<<<(ET + 255) / 256, 256>>>(src, dst, ew);
    k_sortrow<<<32, 256>>>();
    cudaEventRecord(evCSR, 0);

    // s2: fp64 exact pipeline (after CSR)
    cudaStreamWaitEvent(s2, evCSR, 0);
    k_degs_d<<<32, 256, 0, s2>>>();
    k_xpool_d<<<Nn / 8, 256, 0, s2>>>(b_gcn);
    k_xqa12_d<<<Nn / 8, 256, 0, s2>>>(Wa);
    k_soft_d<<<Nn / 8, 256, 0, s2>>>(ba);
    k_outled_d<<<Nn / 8, 256, 0, s2>>>(x, W_le, W_le1, W_le2);
    k_fit_d<<<Nn / 8, 256, 0, s2>>>(b_le1, b_le2);
    k_sortd_chunk<<<16, 256, 0, s2>>>();
    k_rankx<<<32, 256, 0, s2>>>();
    k_gap<<<1, 1024, 0, s2>>>();
    cudaEventRecord(evJoin, s2);

    // stream0: fp32 emulation pipeline (concurrent with s2)
    k_deg<<<32, 256>>>();
    cudaStreamWaitEvent(0, evH, 0);             // g_h ready
    k_xpool<<<Nn, Cc>>>(b_gcn);
    k_xqmq<<<Nn, Cc>>>(Wq, bq, Wa);
    k_s<<<(ET + 255) / 256, 256>>>(Wa, ba);
    k_soft<<<Nn / 8, 256>>>(att_o);
    k_outhl<<<Nn, Cc>>>(x, W_le, W_le1, b_le1, W_le2, b_le2);
    k_fit<<<32, 256>>>();
    k_sorte_chunk<<<16, 256>>>();
    k_ranke2<<<32, 256>>>();

    // join + finalize
    cudaStreamWaitEvent(0, evJoin, 0);
    k_fix<<<1, 1>>>();
    k_finalize<<<KN / 256, 256>>>(perm_o);
    cudaEventRecord(evFix, 0);

    // s2: xout overlaps the S/Emat tail
    cudaStreamWaitEvent(s2, evFix, 0);
    k_xout<<<KN, Cc, 0, s2>>>(xout_o);
    cudaEventRecord(evJoin, s2);

    // stream0: S, Emat
    k_sval<<<(ET + 255) / 256, 256>>>(src, dst, ew, att_o, sval_o);
    {
        int* d_scnt; cudaGetSymbolAddress((void**)&d_scnt, g_scnt);
        int* d_soff; cudaGetSymbolAddress((void**)&d_soff, g_soff);
        int* d_scur; cudaGetSymbolAddress((void**)&d_scur, g_scur);
        k_scan<<<1, 1024>>>(d_scnt, d_soff, d_scur);
    }
    k_sdscat<<<(ET + 255) / 256, 256>>>(src, dst, ew, att_o);
    k_emat<<<(ET + 255) / 256, 256>>>(src, dst, ew, emat_o);
    k_diag<<<KN / 256, 256>>>(emat_o);

    // final join so all forked work lands back on the origin stream
    cudaStreamWaitEvent(0, evJoin, 0);
}